// round 1
// baseline (speedup 1.0000x reference)
#include <cuda_runtime.h>
#include <math.h>

// ---------------- problem constants ----------------
#define BB 2
#define TT 2048
#define DD 1024
#define HH 16
#define HD 64
#define STRIDE 8
#define MLPD 4096
#define BT (BB*TT)          // 4096 rows
#define D3 (3*DD)           // 3072

// ---------------- scratch (static device allocs; no cudaMalloc allowed) ----
__device__ float g_xn [BT*DD];     // LN1 output
__device__ float g_qkv[BT*D3];     // fused qkv
__device__ float g_o  [BT*DD];     // attention output (pre out-proj)
__device__ float g_x2 [BT*DD];     // x + attn_out
__device__ float g_xn2[BT*DD];     // LN2 output
__device__ float g_h  [BT*MLPD];   // gelu(mlp1)

// ---------------- LayerNorm: one block per row ----------------
__global__ __launch_bounds__(256) void ln_kernel(
    const float* __restrict__ x, const float* __restrict__ g,
    const float* __restrict__ b, float* __restrict__ y)
{
    const int row = blockIdx.x;
    const int tid = threadIdx.x;
    const float4* xr = (const float4*)(x + (size_t)row * DD);
    float4 v = xr[tid];                 // 256 threads * 4 = 1024

    float s  = v.x + v.y + v.z + v.w;
    float sq = v.x*v.x + v.y*v.y + v.z*v.z + v.w*v.w;

    __shared__ float red_s[8], red_q[8];
    // warp reduce
    for (int o = 16; o > 0; o >>= 1) {
        s  += __shfl_xor_sync(0xffffffffu, s,  o);
        sq += __shfl_xor_sync(0xffffffffu, sq, o);
    }
    const int wid = tid >> 5, lid = tid & 31;
    if (lid == 0) { red_s[wid] = s; red_q[wid] = sq; }
    __syncthreads();
    if (tid == 0) {
        float ts = 0.f, tq = 0.f;
        #pragma unroll
        for (int i = 0; i < 8; i++) { ts += red_s[i]; tq += red_q[i]; }
        red_s[0] = ts * (1.0f / DD);
        red_q[0] = tq * (1.0f / DD);
    }
    __syncthreads();
    const float mean = red_s[0];
    const float var  = red_q[0] - mean * mean;
    const float rstd = rsqrtf(var + 1e-5f);

    const float4 gg = ((const float4*)g)[tid];
    const float4 bb = ((const float4*)b)[tid];
    float4 o;
    o.x = (v.x - mean) * rstd * gg.x + bb.x;
    o.y = (v.y - mean) * rstd * gg.y + bb.y;
    o.z = (v.z - mean) * rstd * gg.z + bb.z;
    o.w = (v.w - mean) * rstd * gg.w + bb.w;
    ((float4*)(y + (size_t)row * DD))[tid] = o;
}

// ---------------- SGEMM (NT): C[M,N] = A[M,K] @ W[N,K]^T + bias (+R) (gelu) -
// tiles: 128x64, BK=16, 256 threads, 8x4 per-thread microtile.
#define BM 128
#define BN 64
#define BK 16

template<bool GELU, bool RES>
__global__ __launch_bounds__(256) void gemm_nt(
    const float* __restrict__ A, const float* __restrict__ W,
    const float* __restrict__ bias, const float* __restrict__ R,
    float* __restrict__ C, int M, int N, int K)
{
    __shared__ float As[BK][BM + 4];
    __shared__ float Bs[BK][BN + 4];

    const int t  = threadIdx.x;
    const int m0 = blockIdx.y * BM;
    const int n0 = blockIdx.x * BN;
    const int tx = t & 15;          // 0..15 -> 4 cols each
    const int ty = t >> 4;          // 0..15 -> 8 rows each

    const int lr = t >> 2;          // 0..63 (load row)
    const int lk = (t & 3) * 4;     // 0,4,8,12 (load k)

    float acc[8][4];
    #pragma unroll
    for (int i = 0; i < 8; i++)
        #pragma unroll
        for (int j = 0; j < 4; j++) acc[i][j] = 0.f;

    for (int k0 = 0; k0 < K; k0 += BK) {
        // load A tile (128x16): 2 float4 per thread
        float4 a0 = *(const float4*)(A + (size_t)(m0 + lr)      * K + k0 + lk);
        float4 a1 = *(const float4*)(A + (size_t)(m0 + lr + 64) * K + k0 + lk);
        // load W tile (64x16): 1 float4 per thread
        float4 w0 = *(const float4*)(W + (size_t)(n0 + lr)      * K + k0 + lk);

        As[lk+0][lr]      = a0.x; As[lk+1][lr]      = a0.y;
        As[lk+2][lr]      = a0.z; As[lk+3][lr]      = a0.w;
        As[lk+0][lr + 64] = a1.x; As[lk+1][lr + 64] = a1.y;
        As[lk+2][lr + 64] = a1.z; As[lk+3][lr + 64] = a1.w;
        Bs[lk+0][lr] = w0.x; Bs[lk+1][lr] = w0.y;
        Bs[lk+2][lr] = w0.z; Bs[lk+3][lr] = w0.w;
        __syncthreads();

        #pragma unroll
        for (int kk = 0; kk < BK; kk++) {
            float a[8], b[4];
            #pragma unroll
            for (int i = 0; i < 8; i++) a[i] = As[kk][ty * 8 + i];
            #pragma unroll
            for (int j = 0; j < 4; j++) b[j] = Bs[kk][tx * 4 + j];
            #pragma unroll
            for (int i = 0; i < 8; i++)
                #pragma unroll
                for (int j = 0; j < 4; j++)
                    acc[i][j] += a[i] * b[j];
        }
        __syncthreads();
    }

    #pragma unroll
    for (int i = 0; i < 8; i++) {
        const int row = m0 + ty * 8 + i;
        #pragma unroll
        for (int j = 0; j < 4; j++) {
            const int col = n0 + tx * 4 + j;
            float v = acc[i][j] + bias[col];
            if (GELU) v = 0.5f * v * (1.0f + erff(v * 0.70710678118654752f));
            if (RES)  v += R[(size_t)row * N + col];
            C[(size_t)row * N + col] = v;
        }
    }
}

// ---------------- non-global rows: o = v ----------------
__global__ __launch_bounds__(256) void copy_v_kernel(float* __restrict__ o,
                                                     const float* __restrict__ qkv)
{
    const int idx = blockIdx.x * 256 + threadIdx.x;   // over BT*DD
    const int d   = idx & (DD - 1);
    const int row = idx >> 10;                        // b*T + t
    const int tt  = row & (TT - 1);
    if ((tt & (STRIDE - 1)) != 0) {
        o[idx] = qkv[(size_t)row * D3 + 2 * DD + d];
    }
}

// ---------------- global rows: full softmax attention ----------------
// grid: B*H*(T/STRIDE) blocks, 256 threads. smem scores[T].
__global__ __launch_bounds__(256) void attn_global_kernel(
    float* __restrict__ o, const float* __restrict__ qkv)
{
    __shared__ float sc[TT];
    __shared__ float qs[HD];
    __shared__ float red[8];
    __shared__ float pv[4][HD];
    __shared__ float s_inv;

    const int tid = threadIdx.x;
    const int blk = blockIdx.x;
    const int nG  = TT / STRIDE;                 // 256 global rows per (b,h)
    const int qi  = blk % nG;
    const int h   = (blk / nG) % HH;
    const int b   = blk / (nG * HH);
    const int tq  = qi * STRIDE;

    const float* qp = qkv + (size_t)(b * TT + tq) * D3 + h * HD;          // q
    if (tid < HD / 4) ((float4*)qs)[tid] = ((const float4*)qp)[tid];
    __syncthreads();

    // phase 1: scores
    for (int tk = tid; tk < TT; tk += 256) {
        const float4* kp = (const float4*)(qkv + (size_t)(b * TT + tk) * D3 + DD + h * HD);
        float dot = 0.f;
        #pragma unroll
        for (int i = 0; i < HD / 4; i++) {
            float4 kv = kp[i];
            float4 qv = ((const float4*)qs)[i];
            dot += qv.x*kv.x + qv.y*kv.y + qv.z*kv.z + qv.w*kv.w;
        }
        sc[tk] = dot * 0.125f;                   // 1/sqrt(64)
    }
    __syncthreads();

    // phase 2: softmax (max, exp, sum)
    float mx = -1e30f;
    for (int tk = tid; tk < TT; tk += 256) mx = fmaxf(mx, sc[tk]);
    for (int off = 16; off > 0; off >>= 1) mx = fmaxf(mx, __shfl_xor_sync(0xffffffffu, mx, off));
    const int wid = tid >> 5, lid = tid & 31;
    if (lid == 0) red[wid] = mx;
    __syncthreads();
    if (tid == 0) {
        float m = red[0];
        #pragma unroll
        for (int i = 1; i < 8; i++) m = fmaxf(m, red[i]);
        red[0] = m;
    }
    __syncthreads();
    mx = red[0];
    __syncthreads();

    float lsum = 0.f;
    for (int tk = tid; tk < TT; tk += 256) {
        float e = expf(sc[tk] - mx);
        sc[tk] = e;
        lsum += e;
    }
    for (int off = 16; off > 0; off >>= 1) lsum += __shfl_xor_sync(0xffffffffu, lsum, off);
    if (lid == 0) red[wid] = lsum;
    __syncthreads();
    if (tid == 0) {
        float s = 0.f;
        #pragma unroll
        for (int i = 0; i < 8; i++) s += red[i];
        s_inv = 1.0f / s;
    }
    __syncthreads();

    // phase 3: o = P @ V  (64 dims x 4 key-groups)
    const int d   = tid & (HD - 1);
    const int grp = tid >> 6;                    // 0..3, each covers 512 keys
    float accv = 0.f;
    const float* vbase = qkv + 2 * DD + h * HD + d;
    for (int i = 0; i < TT / 4; i++) {
        const int tk = grp * (TT / 4) + i;
        accv += sc[tk] * vbase[(size_t)(b * TT + tk) * D3];
    }
    pv[grp][d] = accv;
    __syncthreads();
    if (tid < HD) {
        float s = pv[0][tid] + pv[1][tid] + pv[2][tid] + pv[3][tid];
        o[(size_t)(b * TT + tq) * DD + h * HD + tid] = s * s_inv;
    }
}

// ---------------- launch ----------------
extern "C" void kernel_launch(void* const* d_in, const int* in_sizes, int n_in,
                              void* d_out, int out_size)
{
    const float* x     = (const float*)d_in[0];
    const float* w_in  = (const float*)d_in[1];
    const float* b_in  = (const float*)d_in[2];
    const float* w_out = (const float*)d_in[3];
    const float* b_out = (const float*)d_in[4];
    const float* w1    = (const float*)d_in[5];
    const float* b1    = (const float*)d_in[6];
    const float* w2    = (const float*)d_in[7];
    const float* b2    = (const float*)d_in[8];
    const float* ln1_g = (const float*)d_in[9];
    const float* ln1_b = (const float*)d_in[10];
    const float* ln2_g = (const float*)d_in[11];
    const float* ln2_b = (const float*)d_in[12];
    float* out = (float*)d_out;

    float *xn, *qkv, *o, *x2, *xn2, *hbuf;
    cudaGetSymbolAddress((void**)&xn,   g_xn);
    cudaGetSymbolAddress((void**)&qkv,  g_qkv);
    cudaGetSymbolAddress((void**)&o,    g_o);
    cudaGetSymbolAddress((void**)&x2,   g_x2);
    cudaGetSymbolAddress((void**)&xn2,  g_xn2);
    cudaGetSymbolAddress((void**)&hbuf, g_h);

    // 1. LN1
    ln_kernel<<<BT, 256>>>(x, ln1_g, ln1_b, xn);
    // 2. QKV: [4096,1024] @ [3072,1024]^T
    gemm_nt<false,false><<<dim3(D3/BN, BT/BM), 256>>>(xn, w_in, b_in, nullptr, qkv, BT, D3, DD);
    // 3. attention: non-global rows copy v; global rows full softmax
    copy_v_kernel<<<(BT*DD)/256, 256>>>(o, qkv);
    attn_global_kernel<<<BB*HH*(TT/STRIDE), 256>>>(o, qkv);
    // 4. out-proj + residual: x2 = x + o @ w_out^T + b_out
    gemm_nt<false,true><<<dim3(DD/BN, BT/BM), 256>>>(o, w_out, b_out, x, x2, BT, DD, DD);
    // 5. LN2
    ln_kernel<<<BT, 256>>>(x2, ln2_g, ln2_b, xn2);
    // 6. MLP1 + exact GELU: h = gelu(xn2 @ w1^T + b1)
    gemm_nt<true,false><<<dim3(MLPD/BN, BT/BM), 256>>>(xn2, w1, b1, nullptr, hbuf, BT, MLPD, DD);
    // 7. MLP2 + residual: out = x2 + h @ w2^T + b2
    gemm_nt<false,true><<<dim3(DD/BN, BT/BM), 256>>>(hbuf, w2, b2, x2, out, BT, DD, MLPD);
}

// round 3
// speedup vs baseline: 1.6233x; 1.6233x over previous
#include <cuda_runtime.h>
#include <cuda_bf16.h>
#include <math.h>
#include <stdint.h>

// ---------------- problem constants ----------------
#define BB 2
#define TT 2048
#define DD 1024
#define HH 16
#define HD 64
#define STRIDE 8
#define MLPD 4096
#define BT (BB*TT)          // 4096 rows
#define D3 (3*DD)           // 3072

// ---------------- scratch buffers (static device memory) ----------------
__device__ __nv_bfloat16 g_xn_h [BT*DD],  g_xn_l [BT*DD];
__device__ __nv_bfloat16 g_o_h  [BT*DD],  g_o_l  [BT*DD];
__device__ __nv_bfloat16 g_xn2_h[BT*DD],  g_xn2_l[BT*DD];
__device__ __nv_bfloat16 g_h_h  [BT*MLPD],g_h_l  [BT*MLPD];
__device__ __nv_bfloat16 g_win_h[D3*DD],  g_win_l[D3*DD];
__device__ __nv_bfloat16 g_wout_h[DD*DD], g_wout_l[DD*DD];
__device__ __nv_bfloat16 g_w1_h [MLPD*DD],g_w1_l [MLPD*DD];
__device__ __nv_bfloat16 g_w2_h [DD*MLPD],g_w2_l [DD*MLPD];
__device__ float g_qkv[BT*D3];
__device__ float g_x2 [BT*DD];

// ---------------- helpers ----------------
__device__ __forceinline__ uint32_t smem_u32(const void* p) {
    uint32_t a;
    asm("{ .reg .u64 t; cvta.to.shared.u64 t, %1; cvt.u32.u64 %0, t; }" : "=r"(a) : "l"(p));
    return a;
}
__device__ __forceinline__ void cp16(uint32_t dst, const void* src) {
    asm volatile("cp.async.cg.shared.global [%0], [%1], 16;" :: "r"(dst), "l"(src) : "memory");
}
__device__ __forceinline__ void ldmx4(uint32_t* r, uint32_t addr) {
    asm volatile("ldmatrix.sync.aligned.m8n8.x4.shared.b16 {%0,%1,%2,%3}, [%4];"
        : "=r"(r[0]), "=r"(r[1]), "=r"(r[2]), "=r"(r[3]) : "r"(addr));
}
__device__ __forceinline__ void ldmx2(uint32_t* r, uint32_t addr) {
    asm volatile("ldmatrix.sync.aligned.m8n8.x2.shared.b16 {%0,%1}, [%2];"
        : "=r"(r[0]), "=r"(r[1]) : "r"(addr));
}
__device__ __forceinline__ void mma_bf16(float* c, const uint32_t* a, const uint32_t* b) {
    asm volatile("mma.sync.aligned.m16n8k16.row.col.f32.bf16.bf16.f32 "
        "{%0,%1,%2,%3}, {%4,%5,%6,%7}, {%8,%9}, {%0,%1,%2,%3};"
        : "+f"(c[0]), "+f"(c[1]), "+f"(c[2]), "+f"(c[3])
        : "r"(a[0]), "r"(a[1]), "r"(a[2]), "r"(a[3]), "r"(b[0]), "r"(b[1]));
}
__device__ __forceinline__ void split2(float v, __nv_bfloat16& h, __nv_bfloat16& l) {
    h = __float2bfloat16(v);
    l = __float2bfloat16(v - __bfloat162float(h));
}

// ---------------- bf16x3 HMMA GEMM: C[M,N] = A @ W^T (+bias)(+gelu)(+res) ----
// CTA tile 128x128, BK=32, 3-stage cp.async pipeline, 8 warps (2M x 4N).
#define GM 128
#define GN 128
#define GK 32
#define LDT 40                       // bf16 elems per smem row (32 + 8 pad)
#define ROWB (LDT*2)                 // 80 bytes per row
#define TILE_B (128*ROWB)            // 10240 bytes per tile
#define STAGE_B (4*TILE_B)           // Ah|Al|Wh|Wl = 40960
#define NSTAGE 3
#define GEMM_SMEM (NSTAGE*STAGE_B)   // 122880

template<bool GELU_, bool RES_, bool SPLIT_>
__global__ void __launch_bounds__(256) gemm_bf16x3(
    const __nv_bfloat16* __restrict__ Ah, const __nv_bfloat16* __restrict__ Al,
    const __nv_bfloat16* __restrict__ Wh, const __nv_bfloat16* __restrict__ Wl,
    const float* __restrict__ bias, const float* __restrict__ Rres,
    float* __restrict__ C, __nv_bfloat16* __restrict__ Ch, __nv_bfloat16* __restrict__ Cl,
    int N, int K)
{
    extern __shared__ char smem[];
    const uint32_t sb = smem_u32(smem);
    const int t = threadIdx.x;
    const int wid = t >> 5, lane = t & 31;
    const int m0 = blockIdx.y * GM;
    const int n0 = blockIdx.x * GN;
    const int wm = (wid & 1) * 64;       // warp M offset
    const int wn = (wid >> 1) * 32;      // warp N offset

    const int row = t >> 2;              // 0..63  (load row within 64-row half)
    const int kc  = t & 3;               // 16B chunk within 64B row
    const uint32_t soff = (uint32_t)(row * ROWB + kc * 16);

    const int nch = K / GK;

    auto load_stage = [&](int chunk, int s) {
        const uint32_t base = sb + s * STAGE_B;
        const size_t k0 = (size_t)chunk * GK + kc * 8;
        #pragma unroll
        for (int j = 0; j < 2; j++) {
            const int r = row + j * 64;
            const uint32_t so = soff + j * 64 * ROWB;
            const size_t ga = (size_t)(m0 + r) * K + k0;
            const size_t gw = (size_t)(n0 + r) * K + k0;
            cp16(base + so,              Ah + ga);
            cp16(base + TILE_B + so,     Al + ga);
            cp16(base + 2*TILE_B + so,   Wh + gw);
            cp16(base + 3*TILE_B + so,   Wl + gw);
        }
        asm volatile("cp.async.commit_group;" ::: "memory");
    };

    float acc[4][4][4];
    #pragma unroll
    for (int i = 0; i < 4; i++)
        #pragma unroll
        for (int j = 0; j < 4; j++)
            #pragma unroll
            for (int k = 0; k < 4; k++) acc[i][j][k] = 0.f;

    load_stage(0, 0);
    load_stage(1, 1);

    // ldmatrix lane addressing
    const int la_row = lane & 15;            // A: m row within 16
    const int la_kh  = (lane >> 4) * 8;      // A: k half
    const int lb     = lane & 15;
    const int lb_row = lb & 7;               // B: n row within 8
    const int lb_kh  = (lb >> 3) * 8;        // B: k half

    for (int i = 0; i < nch; i++) {
        asm volatile("cp.async.wait_group 1;" ::: "memory");
        __syncthreads();
        if (i + 2 < nch) load_stage(i + 2, (i + 2) % NSTAGE);

        const uint32_t st = sb + (i % NSTAGE) * STAGE_B;
        const uint32_t aBh = st;
        const uint32_t aBl = st + TILE_B;
        const uint32_t wBh = st + 2*TILE_B;
        const uint32_t wBl = st + 3*TILE_B;

        #pragma unroll
        for (int kk = 0; kk < 2; kk++) {     // two k16 steps per GK=32
            const uint32_t ko = (uint32_t)(kk * 16 + la_kh) * 2;
            const uint32_t kob = (uint32_t)(kk * 16 + lb_kh) * 2;
            uint32_t ah[4][4], al[4][4];
            #pragma unroll
            for (int mf = 0; mf < 4; mf++) {
                const uint32_t ro = (uint32_t)(wm + mf * 16 + la_row) * ROWB + ko;
                ldmx4(ah[mf], aBh + ro);
                ldmx4(al[mf], aBl + ro);
            }
            uint32_t bh[4][2], bl[4][2];
            #pragma unroll
            for (int nf = 0; nf < 4; nf++) {
                const uint32_t ro = (uint32_t)(wn + nf * 8 + lb_row) * ROWB + kob;
                ldmx2(bh[nf], wBh + ro);
                ldmx2(bl[nf], wBl + ro);
            }
            #pragma unroll
            for (int mf = 0; mf < 4; mf++)
                #pragma unroll
                for (int nf = 0; nf < 4; nf++) {
                    mma_bf16(acc[mf][nf], ah[mf], bh[nf]);
                    mma_bf16(acc[mf][nf], ah[mf], bl[nf]);
                    mma_bf16(acc[mf][nf], al[mf], bh[nf]);
                }
        }
    }

    // ---- epilogue: direct register -> gmem
    const int er = lane >> 2;            // 0..7
    const int ec = (lane & 3) * 2;       // 0,2,4,6
    #pragma unroll
    for (int mf = 0; mf < 4; mf++) {
        #pragma unroll
        for (int nf = 0; nf < 4; nf++) {
            const int c0 = n0 + wn + nf * 8 + ec;
            const float b0 = bias[c0], b1 = bias[c0 + 1];
            #pragma unroll
            for (int half = 0; half < 2; half++) {
                const int r = m0 + wm + mf * 16 + er + half * 8;
                float v0 = acc[mf][nf][half * 2 + 0] + b0;
                float v1 = acc[mf][nf][half * 2 + 1] + b1;
                if (GELU_) {
                    v0 = 0.5f * v0 * (1.0f + erff(v0 * 0.70710678118654752f));
                    v1 = 0.5f * v1 * (1.0f + erff(v1 * 0.70710678118654752f));
                }
                if (RES_) {
                    v0 += Rres[(size_t)r * N + c0];
                    v1 += Rres[(size_t)r * N + c0 + 1];
                }
                if (SPLIT_) {
                    __nv_bfloat16 h0, l0, h1, l1;
                    split2(v0, h0, l0); split2(v1, h1, l1);
                    __nv_bfloat162 ph; ph.x = h0; ph.y = h1;
                    __nv_bfloat162 pl; pl.x = l0; pl.y = l1;
                    *(__nv_bfloat162*)(Ch + (size_t)r * N + c0) = ph;
                    *(__nv_bfloat162*)(Cl + (size_t)r * N + c0) = pl;
                } else {
                    float2 p; p.x = v0; p.y = v1;
                    *(float2*)(C + (size_t)r * N + c0) = p;
                }
            }
        }
    }
}

// ---------------- LayerNorm -> split bf16 hi/lo ----------------
__global__ __launch_bounds__(256) void ln_split_kernel(
    const float* __restrict__ x, const float* __restrict__ g, const float* __restrict__ b,
    __nv_bfloat16* __restrict__ yh, __nv_bfloat16* __restrict__ yl)
{
    const int row = blockIdx.x;
    const int tid = threadIdx.x;
    float4 v = ((const float4*)(x + (size_t)row * DD))[tid];

    float s  = v.x + v.y + v.z + v.w;
    float sq = v.x*v.x + v.y*v.y + v.z*v.z + v.w*v.w;
    __shared__ float red_s[8], red_q[8];
    for (int o = 16; o > 0; o >>= 1) {
        s  += __shfl_xor_sync(0xffffffffu, s,  o);
        sq += __shfl_xor_sync(0xffffffffu, sq, o);
    }
    const int wid = tid >> 5, lid = tid & 31;
    if (lid == 0) { red_s[wid] = s; red_q[wid] = sq; }
    __syncthreads();
    if (tid == 0) {
        float ts = 0.f, tq = 0.f;
        #pragma unroll
        for (int i = 0; i < 8; i++) { ts += red_s[i]; tq += red_q[i]; }
        red_s[0] = ts * (1.0f / DD);
        red_q[0] = tq * (1.0f / DD);
    }
    __syncthreads();
    const float mean = red_s[0];
    const float rstd = rsqrtf(red_q[0] - mean * mean + 1e-5f);

    const float4 gg = ((const float4*)g)[tid];
    const float4 bb = ((const float4*)b)[tid];
    float o0 = (v.x - mean) * rstd * gg.x + bb.x;
    float o1 = (v.y - mean) * rstd * gg.y + bb.y;
    float o2 = (v.z - mean) * rstd * gg.z + bb.z;
    float o3 = (v.w - mean) * rstd * gg.w + bb.w;
    __nv_bfloat16 h0,h1,h2,h3,l0,l1,l2,l3;
    split2(o0,h0,l0); split2(o1,h1,l1); split2(o2,h2,l2); split2(o3,h3,l3);
    __nv_bfloat162* ph = (__nv_bfloat162*)(yh + (size_t)row * DD);
    __nv_bfloat162* pl = (__nv_bfloat162*)(yl + (size_t)row * DD);
    __nv_bfloat162 a; a.x=h0; a.y=h1; ph[2*tid]   = a;
    a.x=h2; a.y=h3;            ph[2*tid+1] = a;
    a.x=l0; a.y=l1;            pl[2*tid]   = a;
    a.x=l2; a.y=l3;            pl[2*tid+1] = a;
}

// ---------------- fp32 -> bf16 hi/lo split (weights) ----------------
__global__ __launch_bounds__(256) void split_kernel(
    const float* __restrict__ src, __nv_bfloat16* __restrict__ h,
    __nv_bfloat16* __restrict__ l, int n4)
{
    int i = blockIdx.x * 256 + threadIdx.x;
    if (i >= n4) return;
    float4 v = ((const float4*)src)[i];
    __nv_bfloat16 h0,h1,h2,h3,l0,l1,l2,l3;
    split2(v.x,h0,l0); split2(v.y,h1,l1); split2(v.z,h2,l2); split2(v.w,h3,l3);
    __nv_bfloat162 a;
    a.x=h0; a.y=h1; ((__nv_bfloat162*)h)[2*i]   = a;
    a.x=h2; a.y=h3; ((__nv_bfloat162*)h)[2*i+1] = a;
    a.x=l0; a.y=l1; ((__nv_bfloat162*)l)[2*i]   = a;
    a.x=l2; a.y=l3; ((__nv_bfloat162*)l)[2*i+1] = a;
}

// ---------------- non-global rows: o = v (split) ----------------
__global__ __launch_bounds__(256) void copy_v_split_kernel(
    __nv_bfloat16* __restrict__ oh, __nv_bfloat16* __restrict__ ol,
    const float* __restrict__ qkv)
{
    const int idx = blockIdx.x * 256 + threadIdx.x;
    const int d   = idx & (DD - 1);
    const int row = idx >> 10;
    const int tt  = row & (TT - 1);
    if ((tt & (STRIDE - 1)) != 0) {
        float v = qkv[(size_t)row * D3 + 2 * DD + d];
        __nv_bfloat16 h, l; split2(v, h, l);
        oh[idx] = h; ol[idx] = l;
    }
}

// ---------------- global rows: full softmax attention ----------------
__global__ __launch_bounds__(256) void attn_global_kernel(
    __nv_bfloat16* __restrict__ oh, __nv_bfloat16* __restrict__ ol,
    const float* __restrict__ qkv)
{
    __shared__ float sc[TT];
    __shared__ float qs[HD];
    __shared__ float red[8];
    __shared__ float pv[4][HD];
    __shared__ float s_inv;

    const int tid = threadIdx.x;
    const int blk = blockIdx.x;
    const int nG  = TT / STRIDE;
    const int qi  = blk % nG;
    const int h   = (blk / nG) % HH;
    const int b   = blk / (nG * HH);
    const int tq  = qi * STRIDE;

    const float* qp = qkv + (size_t)(b * TT + tq) * D3 + h * HD;
    if (tid < HD / 4) ((float4*)qs)[tid] = ((const float4*)qp)[tid];
    __syncthreads();

    for (int tk = tid; tk < TT; tk += 256) {
        const float4* kp = (const float4*)(qkv + (size_t)(b * TT + tk) * D3 + DD + h * HD);
        float dot = 0.f;
        #pragma unroll
        for (int i = 0; i < HD / 4; i++) {
            float4 kv = kp[i];
            float4 qv = ((const float4*)qs)[i];
            dot += qv.x*kv.x + qv.y*kv.y + qv.z*kv.z + qv.w*kv.w;
        }
        sc[tk] = dot * 0.125f;
    }
    __syncthreads();

    float mx = -1e30f;
    for (int tk = tid; tk < TT; tk += 256) mx = fmaxf(mx, sc[tk]);
    for (int off = 16; off > 0; off >>= 1) mx = fmaxf(mx, __shfl_xor_sync(0xffffffffu, mx, off));
    const int wid = tid >> 5, lid = tid & 31;
    if (lid == 0) red[wid] = mx;
    __syncthreads();
    if (tid == 0) {
        float m = red[0];
        #pragma unroll
        for (int i = 1; i < 8; i++) m = fmaxf(m, red[i]);
        red[0] = m;
    }
    __syncthreads();
    mx = red[0];
    __syncthreads();

    float lsum = 0.f;
    for (int tk = tid; tk < TT; tk += 256) {
        float e = expf(sc[tk] - mx);
        sc[tk] = e;
        lsum += e;
    }
    for (int off = 16; off > 0; off >>= 1) lsum += __shfl_xor_sync(0xffffffffu, lsum, off);
    if (lid == 0) red[wid] = lsum;
    __syncthreads();
    if (tid == 0) {
        float sum = 0.f;
        #pragma unroll
        for (int i = 0; i < 8; i++) sum += red[i];
        s_inv = 1.0f / sum;
    }
    __syncthreads();

    const int d   = tid & (HD - 1);
    const int grp = tid >> 6;
    float accv = 0.f;
    const float* vbase = qkv + 2 * DD + h * HD + d;
    for (int i = 0; i < TT / 4; i++) {
        const int tk = grp * (TT / 4) + i;
        accv += sc[tk] * vbase[(size_t)(b * TT + tk) * D3];
    }
    pv[grp][d] = accv;
    __syncthreads();
    if (tid < HD) {
        float v = (pv[0][tid] + pv[1][tid] + pv[2][tid] + pv[3][tid]) * s_inv;
        __nv_bfloat16 hh, ll; split2(v, hh, ll);
        const size_t base = (size_t)(b * TT + tq) * DD + h * HD + tid;
        oh[base] = hh; ol[base] = ll;
    }
}

// ---------------- launch ----------------
extern "C" void kernel_launch(void* const* d_in, const int* in_sizes, int n_in,
                              void* d_out, int out_size)
{
    const float* x     = (const float*)d_in[0];
    const float* w_in  = (const float*)d_in[1];
    const float* b_in  = (const float*)d_in[2];
    const float* w_out = (const float*)d_in[3];
    const float* b_out = (const float*)d_in[4];
    const float* w1    = (const float*)d_in[5];
    const float* b1    = (const float*)d_in[6];
    const float* w2    = (const float*)d_in[7];
    const float* b2    = (const float*)d_in[8];
    const float* ln1_g = (const float*)d_in[9];
    const float* ln1_b = (const float*)d_in[10];
    const float* ln2_g = (const float*)d_in[11];
    const float* ln2_b = (const float*)d_in[12];
    float* out = (float*)d_out;

    __nv_bfloat16 *xnh,*xnl,*oh,*ol,*xn2h,*xn2l,*hh,*hl;
    __nv_bfloat16 *winh,*winl,*wouth,*woutl,*w1h,*w1l,*w2h,*w2l;
    float *qkv, *x2;
    cudaGetSymbolAddress((void**)&xnh,  g_xn_h);   cudaGetSymbolAddress((void**)&xnl,  g_xn_l);
    cudaGetSymbolAddress((void**)&oh,   g_o_h);    cudaGetSymbolAddress((void**)&ol,   g_o_l);
    cudaGetSymbolAddress((void**)&xn2h, g_xn2_h);  cudaGetSymbolAddress((void**)&xn2l, g_xn2_l);
    cudaGetSymbolAddress((void**)&hh,   g_h_h);    cudaGetSymbolAddress((void**)&hl,   g_h_l);
    cudaGetSymbolAddress((void**)&winh, g_win_h);  cudaGetSymbolAddress((void**)&winl, g_win_l);
    cudaGetSymbolAddress((void**)&wouth,g_wout_h); cudaGetSymbolAddress((void**)&woutl,g_wout_l);
    cudaGetSymbolAddress((void**)&w1h,  g_w1_h);   cudaGetSymbolAddress((void**)&w1l,  g_w1_l);
    cudaGetSymbolAddress((void**)&w2h,  g_w2_h);   cudaGetSymbolAddress((void**)&w2l,  g_w2_l);
    cudaGetSymbolAddress((void**)&qkv,  g_qkv);
    cudaGetSymbolAddress((void**)&x2,   g_x2);

    cudaFuncSetAttribute(gemm_bf16x3<false,false,false>, cudaFuncAttributeMaxDynamicSharedMemorySize, GEMM_SMEM);
    cudaFuncSetAttribute(gemm_bf16x3<false,true ,false>, cudaFuncAttributeMaxDynamicSharedMemorySize, GEMM_SMEM);
    cudaFuncSetAttribute(gemm_bf16x3<true ,false,true >, cudaFuncAttributeMaxDynamicSharedMemorySize, GEMM_SMEM);

    // 1. LN1 -> split
    ln_split_kernel<<<BT, 256>>>(x, ln1_g, ln1_b, xnh, xnl);
    // 2. split weights
    split_kernel<<<(D3*DD/4 + 255)/256, 256>>>(w_in,  winh,  winl,  D3*DD/4);
    split_kernel<<<(DD*DD/4 + 255)/256, 256>>>(w_out, wouth, woutl, DD*DD/4);
    split_kernel<<<(MLPD*DD/4 + 255)/256, 256>>>(w1,  w1h,   w1l,   MLPD*DD/4);
    split_kernel<<<(DD*MLPD/4 + 255)/256, 256>>>(w2,  w2h,   w2l,   DD*MLPD/4);
    // 3. QKV GEMM -> fp32 qkv
    gemm_bf16x3<false,false,false><<<dim3(D3/GN, BT/GM), 256, GEMM_SMEM>>>(
        xnh, xnl, winh, winl, b_in, nullptr, qkv, nullptr, nullptr, D3, DD);
    // 4. attention
    copy_v_split_kernel<<<(BT*DD)/256, 256>>>(oh, ol, qkv);
    attn_global_kernel<<<BB*HH*(TT/STRIDE), 256>>>(oh, ol, qkv);
    // 5. out-proj + residual -> x2 fp32
    gemm_bf16x3<false,true,false><<<dim3(DD/GN, BT/GM), 256, GEMM_SMEM>>>(
        oh, ol, wouth, woutl, b_out, x, x2, nullptr, nullptr, DD, DD);
    // 6. LN2 -> split
    ln_split_kernel<<<BT, 256>>>(x2, ln2_g, ln2_b, xn2h, xn2l);
    // 7. MLP1 + GELU -> split h
    gemm_bf16x3<true,false,true><<<dim3(MLPD/GN, BT/GM), 256, GEMM_SMEM>>>(
        xn2h, xn2l, w1h, w1l, b1, nullptr, nullptr, hh, hl, MLPD, DD);
    // 8. MLP2 + residual -> out
    gemm_bf16x3<false,true,false><<<dim3(DD/GN, BT/GM), 256, GEMM_SMEM>>>(
        hh, hl, w2h, w2l, b2, x2, out, nullptr, nullptr, DD, MLPD);
}

// round 4
// speedup vs baseline: 6.8766x; 4.2362x over previous
#include <cuda_runtime.h>
#include <cuda_fp16.h>
#include <math.h>
#include <stdint.h>

// ---------------- problem constants ----------------
#define BB 2
#define TT 2048
#define DD 1024
#define HH 16
#define HD 64
#define STRIDE 8
#define MLPD 4096
#define BT (BB*TT)          // 4096 rows
#define D3 (3*DD)           // 3072

// ---------------- scratch buffers (static device memory) ----------------
__device__ __half g_xn [BT*DD];
__device__ __half g_o  [BT*DD];
__device__ __half g_xn2[BT*DD];
__device__ __half g_h  [BT*MLPD];
__device__ __half g_win[D3*DD];
__device__ __half g_wout[DD*DD];
__device__ __half g_w1 [MLPD*DD];
__device__ __half g_w2 [DD*MLPD];
__device__ float g_qkv[BT*D3];
__device__ float g_x2 [BT*DD];

// ---------------- helpers ----------------
__device__ __forceinline__ uint32_t smem_u32(const void* p) {
    uint32_t a;
    asm("{ .reg .u64 t; cvta.to.shared.u64 t, %1; cvt.u32.u64 %0, t; }" : "=r"(a) : "l"(p));
    return a;
}
__device__ __forceinline__ void cp16(uint32_t dst, const void* src) {
    asm volatile("cp.async.cg.shared.global [%0], [%1], 16;" :: "r"(dst), "l"(src) : "memory");
}
__device__ __forceinline__ void ldmx4(uint32_t* r, uint32_t addr) {
    asm volatile("ldmatrix.sync.aligned.m8n8.x4.shared.b16 {%0,%1,%2,%3}, [%4];"
        : "=r"(r[0]), "=r"(r[1]), "=r"(r[2]), "=r"(r[3]) : "r"(addr));
}
__device__ __forceinline__ void ldmx2(uint32_t* r, uint32_t addr) {
    asm volatile("ldmatrix.sync.aligned.m8n8.x2.shared.b16 {%0,%1}, [%2];"
        : "=r"(r[0]), "=r"(r[1]) : "r"(addr));
}
__device__ __forceinline__ void mma_f16(float* c, const uint32_t* a, const uint32_t* b) {
    asm volatile("mma.sync.aligned.m16n8k16.row.col.f32.f16.f16.f32 "
        "{%0,%1,%2,%3}, {%4,%5,%6,%7}, {%8,%9}, {%0,%1,%2,%3};"
        : "+f"(c[0]), "+f"(c[1]), "+f"(c[2]), "+f"(c[3])
        : "r"(a[0]), "r"(a[1]), "r"(a[2]), "r"(a[3]), "r"(b[0]), "r"(b[1]));
}
// XOR swizzle for 64B rows, 16B chunks: conflict-free for ldmatrix & stores
__device__ __forceinline__ uint32_t swz(int r, int c) {
    return (uint32_t)((c ^ (r & 3) ^ ((r >> 2) & 1)) & 3);
}

// ---------------- fp16 HMMA GEMM: C[M,N] = A @ W^T (+bias)(+gelu)(+res) ----
// CTA tile 128x128, GK=32, 4-stage cp.async, 8 warps (2M x 4N), 2 CTAs/SM.
#define GM 128
#define GN 128
#define GK 32
#define STAGE_B 16384               // A 8KB + W 8KB
#define NST 4
#define GEMM_SMEM (NST*STAGE_B)     // 65536

template<bool GELU_, bool RES_, bool F16O_>
__global__ void __launch_bounds__(256, 2) gemm_f16k(
    const __half* __restrict__ A, const __half* __restrict__ W,
    const float* __restrict__ bias, const float* __restrict__ Rres,
    float* __restrict__ C, __half* __restrict__ Cf, int N, int K)
{
    extern __shared__ char smem[];
    const uint32_t sb = smem_u32(smem);
    const int t = threadIdx.x;
    const int wid = t >> 5, lane = t & 31;
    const int m0 = blockIdx.y * GM;
    const int n0 = blockIdx.x * GN;
    const int wm = (wid & 1) * 64;
    const int wn = (wid >> 1) * 32;

    const int lr = t >> 2;          // 0..63 row (per 64-row pass)
    const int lc = t & 3;           // chunk 0..3

    const int nch = K / GK;

    auto load_stage = [&](int chunk, int s) {
        const uint32_t base = sb + s * STAGE_B;
        const size_t k0 = (size_t)chunk * GK + lc * 8;
        #pragma unroll
        for (int j = 0; j < 2; j++) {
            const int r = lr + j * 64;
            const uint32_t so = (uint32_t)(r * 64 + swz(r, lc) * 16);
            cp16(base + so,        A + (size_t)(m0 + r) * K + k0);
            cp16(base + 8192 + so, W + (size_t)(n0 + r) * K + k0);
        }
    };

    float acc[4][4][4];
    #pragma unroll
    for (int i = 0; i < 4; i++)
        #pragma unroll
        for (int j = 0; j < 4; j++)
            #pragma unroll
            for (int k = 0; k < 4; k++) acc[i][j][k] = 0.f;

    load_stage(0, 0); asm volatile("cp.async.commit_group;" ::: "memory");
    load_stage(1, 1); asm volatile("cp.async.commit_group;" ::: "memory");
    load_stage(2, 2); asm volatile("cp.async.commit_group;" ::: "memory");

    const int la_row = lane & 15;
    const int la_kh  = lane >> 4;        // 0/1
    const int lb_row = lane & 7;
    const int lb_kh  = (lane >> 3) & 1;

    for (int i = 0; i < nch; i++) {
        asm volatile("cp.async.wait_group 2;" ::: "memory");
        __syncthreads();
        if (i + 3 < nch) load_stage(i + 3, (i + 3) & 3);
        asm volatile("cp.async.commit_group;" ::: "memory");

        const uint32_t aB = sb + (i & 3) * STAGE_B;
        const uint32_t wB = aB + 8192;

        #pragma unroll
        for (int kk = 0; kk < 2; kk++) {
            uint32_t b[4][2];
            #pragma unroll
            for (int nf = 0; nf < 4; nf++) {
                const int r = wn + nf * 8 + lb_row;
                const int c = kk * 2 + lb_kh;
                ldmx2(b[nf], wB + (uint32_t)(r * 64) + swz(r, c) * 16);
            }
            #pragma unroll
            for (int mf = 0; mf < 4; mf++) {
                uint32_t a[4];
                const int r = wm + mf * 16 + la_row;
                const int c = kk * 2 + la_kh;
                ldmx4(a, aB + (uint32_t)(r * 64) + swz(r, c) * 16);
                #pragma unroll
                for (int nf = 0; nf < 4; nf++)
                    mma_f16(acc[mf][nf], a, b[nf]);
            }
        }
    }

    // ---- epilogue: registers -> gmem
    const int er = lane >> 2;
    const int ec = (lane & 3) * 2;
    #pragma unroll
    for (int mf = 0; mf < 4; mf++) {
        #pragma unroll
        for (int nf = 0; nf < 4; nf++) {
            const int c0 = n0 + wn + nf * 8 + ec;
            const float b0 = bias[c0], b1 = bias[c0 + 1];
            #pragma unroll
            for (int half = 0; half < 2; half++) {
                const int r = m0 + wm + mf * 16 + er + half * 8;
                float v0 = acc[mf][nf][half * 2 + 0] + b0;
                float v1 = acc[mf][nf][half * 2 + 1] + b1;
                if (GELU_) {
                    v0 = 0.5f * v0 * (1.0f + erff(v0 * 0.70710678118654752f));
                    v1 = 0.5f * v1 * (1.0f + erff(v1 * 0.70710678118654752f));
                }
                if (RES_) {
                    v0 += Rres[(size_t)r * N + c0];
                    v1 += Rres[(size_t)r * N + c0 + 1];
                }
                if (F16O_) {
                    *(__half2*)(Cf + (size_t)r * N + c0) = __floats2half2_rn(v0, v1);
                } else {
                    float2 p; p.x = v0; p.y = v1;
                    *(float2*)(C + (size_t)r * N + c0) = p;
                }
            }
        }
    }
}

// ---------------- LayerNorm -> f16 ----------------
__global__ __launch_bounds__(256) void ln_f16_kernel(
    const float* __restrict__ x, const float* __restrict__ g, const float* __restrict__ b,
    __half* __restrict__ y)
{
    const int row = blockIdx.x;
    const int tid = threadIdx.x;
    float4 v = ((const float4*)(x + (size_t)row * DD))[tid];

    float s  = v.x + v.y + v.z + v.w;
    float sq = v.x*v.x + v.y*v.y + v.z*v.z + v.w*v.w;
    __shared__ float red_s[8], red_q[8];
    for (int o = 16; o > 0; o >>= 1) {
        s  += __shfl_xor_sync(0xffffffffu, s,  o);
        sq += __shfl_xor_sync(0xffffffffu, sq, o);
    }
    const int wid = tid >> 5, lid = tid & 31;
    if (lid == 0) { red_s[wid] = s; red_q[wid] = sq; }
    __syncthreads();
    if (tid == 0) {
        float ts = 0.f, tq = 0.f;
        #pragma unroll
        for (int i = 0; i < 8; i++) { ts += red_s[i]; tq += red_q[i]; }
        red_s[0] = ts * (1.0f / DD);
        red_q[0] = tq * (1.0f / DD);
    }
    __syncthreads();
    const float mean = red_s[0];
    const float rstd = rsqrtf(red_q[0] - mean * mean + 1e-5f);

    const float4 gg = ((const float4*)g)[tid];
    const float4 bb = ((const float4*)b)[tid];
    float o0 = (v.x - mean) * rstd * gg.x + bb.x;
    float o1 = (v.y - mean) * rstd * gg.y + bb.y;
    float o2 = (v.z - mean) * rstd * gg.z + bb.z;
    float o3 = (v.w - mean) * rstd * gg.w + bb.w;
    __half2* py = (__half2*)(y + (size_t)row * DD);
    py[2*tid]   = __floats2half2_rn(o0, o1);
    py[2*tid+1] = __floats2half2_rn(o2, o3);
}

// ---------------- fp32 -> fp16 convert (weights) ----------------
__global__ __launch_bounds__(256) void cvt_f16_kernel(
    const float* __restrict__ src, __half* __restrict__ dst, int n4)
{
    int i = blockIdx.x * 256 + threadIdx.x;
    if (i >= n4) return;
    float4 v = ((const float4*)src)[i];
    ((__half2*)dst)[2*i]   = __floats2half2_rn(v.x, v.y);
    ((__half2*)dst)[2*i+1] = __floats2half2_rn(v.z, v.w);
}

// ---------------- non-global rows: o = v ----------------
__global__ __launch_bounds__(256) void copy_v_kernel(
    __half* __restrict__ o, const float* __restrict__ qkv)
{
    const int idx = blockIdx.x * 256 + threadIdx.x;   // over BT*DD
    const int d   = idx & (DD - 1);
    const int row = idx >> 10;
    const int tt  = row & (TT - 1);
    if ((tt & (STRIDE - 1)) != 0) {
        o[idx] = __float2half(qkv[(size_t)row * D3 + 2 * DD + d]);
    }
}

// ---------------- global rows: flash-style attention ----------------
// grid = B*H*8 blocks; block = 256 thr (8 warps, 4 queries/warp, 32 q/block).
// Streams keys in chunks of 128 through smem; online softmax in fp32.
#define AQ 32
#define CK 128
#define KPAD 68
#define ATTN_SMEM (AQ*64*4 + CK*KPAD*4 + CK*64*4 + 8*4*CK*4)   // 92160

__global__ __launch_bounds__(256) void attn_flash_kernel(
    __half* __restrict__ o, const float* __restrict__ qkv)
{
    extern __shared__ char smem[];
    float* Qs = (float*)smem;                         // [32][64]
    float* Ks = Qs + AQ * 64;                         // [128][68]
    float* Vs = Ks + CK * KPAD;                       // [128][64]
    float* Ps = Vs + CK * 64;                         // [8][4][128]

    const int t = threadIdx.x;
    const int wid = t >> 5, lane = t & 31;
    const int blk = blockIdx.x;
    const int qt = blk & 7;
    const int h  = (blk >> 3) & (HH - 1);
    const int b  = blk >> 7;

    // load Q tile (32 queries), pre-scaled by 1/sqrt(64)
    #pragma unroll
    for (int it = 0; it < 2; it++) {
        const int idx = t + it * 256;                 // 512 float4
        const int j = idx >> 4, c = idx & 15;
        const int tq = (qt * AQ + j) * STRIDE;
        float4 qv = *(const float4*)(qkv + (size_t)(b * TT + tq) * D3 + h * HD + c * 4);
        qv.x *= 0.125f; qv.y *= 0.125f; qv.z *= 0.125f; qv.w *= 0.125f;
        *(float4*)(Qs + j * 64 + c * 4) = qv;
    }

    float m[4], l[4], oa[4][2];
    #pragma unroll
    for (int q = 0; q < 4; q++) {
        m[q] = -1e30f; l[q] = 0.f; oa[q][0] = 0.f; oa[q][1] = 0.f;
    }

    for (int ch = 0; ch < TT / CK; ch++) {
        const int k0 = ch * CK;
        // load K, V chunk
        #pragma unroll
        for (int it = 0; it < 8; it++) {
            const int idx = t + it * 256;             // 2048 float4
            const int kk = idx >> 4, c = idx & 15;
            const size_t rb = (size_t)(b * TT + k0 + kk) * D3 + h * HD + c * 4;
            *(float4*)(Ks + kk * KPAD + c * 4) = *(const float4*)(qkv + DD + rb);
            *(float4*)(Vs + kk * 64   + c * 4) = *(const float4*)(qkv + 2 * DD + rb);
        }
        __syncthreads();

        // scores: lane handles keys lane+32*jj
        float s[4][4];
        #pragma unroll
        for (int q = 0; q < 4; q++)
            #pragma unroll
            for (int jj = 0; jj < 4; jj++) s[q][jj] = 0.f;
        const float* qrow = Qs + (wid * 4) * 64;
        #pragma unroll 4
        for (int d4 = 0; d4 < 64; d4 += 4) {
            float4 kv[4];
            #pragma unroll
            for (int jj = 0; jj < 4; jj++)
                kv[jj] = *(const float4*)(Ks + (lane + 32 * jj) * KPAD + d4);
            #pragma unroll
            for (int q = 0; q < 4; q++) {
                float4 qv = *(const float4*)(qrow + q * 64 + d4);
                #pragma unroll
                for (int jj = 0; jj < 4; jj++) {
                    s[q][jj] += qv.x * kv[jj].x + qv.y * kv[jj].y
                              + qv.z * kv[jj].z + qv.w * kv[jj].w;
                }
            }
        }

        // online softmax per query
        #pragma unroll
        for (int q = 0; q < 4; q++) {
            float cm = fmaxf(fmaxf(s[q][0], s[q][1]), fmaxf(s[q][2], s[q][3]));
            for (int off = 16; off > 0; off >>= 1)
                cm = fmaxf(cm, __shfl_xor_sync(0xffffffffu, cm, off));
            const float mnew = fmaxf(m[q], cm);
            const float corr = expf(m[q] - mnew);
            float e0 = expf(s[q][0] - mnew), e1 = expf(s[q][1] - mnew);
            float e2 = expf(s[q][2] - mnew), e3 = expf(s[q][3] - mnew);
            float ls = e0 + e1 + e2 + e3;
            for (int off = 16; off > 0; off >>= 1)
                ls += __shfl_xor_sync(0xffffffffu, ls, off);
            l[q] = l[q] * corr + ls;
            m[q] = mnew;
            oa[q][0] *= corr; oa[q][1] *= corr;
            float* pp = Ps + (wid * 4 + q) * CK;
            pp[lane]      = e0;
            pp[lane + 32] = e1;
            pp[lane + 64] = e2;
            pp[lane + 96] = e3;
        }
        __syncwarp();

        // PV: o[q][d] += sum_k p[q][k] * V[k][d],  d = lane, lane+32
        #pragma unroll 4
        for (int k = 0; k < CK; k++) {
            const float v0 = Vs[k * 64 + lane];
            const float v1 = Vs[k * 64 + lane + 32];
            #pragma unroll
            for (int q = 0; q < 4; q++) {
                const float p = Ps[(wid * 4 + q) * CK + k];
                oa[q][0] += p * v0;
                oa[q][1] += p * v1;
            }
        }
        __syncthreads();
    }

    #pragma unroll
    for (int q = 0; q < 4; q++) {
        const float inv = 1.0f / l[q];
        const int tq = (qt * AQ + wid * 4 + q) * STRIDE;
        const size_t base = (size_t)(b * TT + tq) * DD + h * HD;
        o[base + lane]      = __float2half(oa[q][0] * inv);
        o[base + lane + 32] = __float2half(oa[q][1] * inv);
    }
}

// ---------------- launch ----------------
extern "C" void kernel_launch(void* const* d_in, const int* in_sizes, int n_in,
                              void* d_out, int out_size)
{
    const float* x     = (const float*)d_in[0];
    const float* w_in  = (const float*)d_in[1];
    const float* b_in  = (const float*)d_in[2];
    const float* w_out = (const float*)d_in[3];
    const float* b_out = (const float*)d_in[4];
    const float* w1    = (const float*)d_in[5];
    const float* b1    = (const float*)d_in[6];
    const float* w2    = (const float*)d_in[7];
    const float* b2    = (const float*)d_in[8];
    const float* ln1_g = (const float*)d_in[9];
    const float* ln1_b = (const float*)d_in[10];
    const float* ln2_g = (const float*)d_in[11];
    const float* ln2_b = (const float*)d_in[12];
    float* out = (float*)d_out;

    __half *xn,*o,*xn2,*hbuf,*win,*wout,*w1h,*w2h;
    float *qkv, *x2;
    cudaGetSymbolAddress((void**)&xn,   g_xn);
    cudaGetSymbolAddress((void**)&o,    g_o);
    cudaGetSymbolAddress((void**)&xn2,  g_xn2);
    cudaGetSymbolAddress((void**)&hbuf, g_h);
    cudaGetSymbolAddress((void**)&win,  g_win);
    cudaGetSymbolAddress((void**)&wout, g_wout);
    cudaGetSymbolAddress((void**)&w1h,  g_w1);
    cudaGetSymbolAddress((void**)&w2h,  g_w2);
    cudaGetSymbolAddress((void**)&qkv,  g_qkv);
    cudaGetSymbolAddress((void**)&x2,   g_x2);

    cudaFuncSetAttribute(gemm_f16k<false,false,false>, cudaFuncAttributeMaxDynamicSharedMemorySize, GEMM_SMEM);
    cudaFuncSetAttribute(gemm_f16k<false,true ,false>, cudaFuncAttributeMaxDynamicSharedMemorySize, GEMM_SMEM);
    cudaFuncSetAttribute(gemm_f16k<true ,false,true >, cudaFuncAttributeMaxDynamicSharedMemorySize, GEMM_SMEM);
    cudaFuncSetAttribute(attn_flash_kernel, cudaFuncAttributeMaxDynamicSharedMemorySize, ATTN_SMEM);

    // 1. LN1 -> f16
    ln_f16_kernel<<<BT, 256>>>(x, ln1_g, ln1_b, xn);
    // 2. convert weights -> f16
    cvt_f16_kernel<<<(D3*DD/4 + 255)/256, 256>>>(w_in,  win,  D3*DD/4);
    cvt_f16_kernel<<<(DD*DD/4 + 255)/256, 256>>>(w_out, wout, DD*DD/4);
    cvt_f16_kernel<<<(MLPD*DD/4 + 255)/256, 256>>>(w1,  w1h,  MLPD*DD/4);
    cvt_f16_kernel<<<(DD*MLPD/4 + 255)/256, 256>>>(w2,  w2h,  DD*MLPD/4);
    // 3. QKV GEMM -> fp32 qkv
    gemm_f16k<false,false,false><<<dim3(D3/GN, BT/GM), 256, GEMM_SMEM>>>(
        xn, win, b_in, nullptr, qkv, nullptr, D3, DD);
    // 4. attention
    copy_v_kernel<<<(BT*DD)/256, 256>>>(o, qkv);
    attn_flash_kernel<<<BB*HH*8, 256, ATTN_SMEM>>>(o, qkv);
    // 5. out-proj + residual -> x2 fp32
    gemm_f16k<false,true,false><<<dim3(DD/GN, BT/GM), 256, GEMM_SMEM>>>(
        o, wout, b_out, x, x2, nullptr, DD, DD);
    // 6. LN2 -> f16
    ln_f16_kernel<<<BT, 256>>>(x2, ln2_g, ln2_b, xn2);
    // 7. MLP1 + GELU -> h f16
    gemm_f16k<true,false,true><<<dim3(MLPD/GN, BT/GM), 256, GEMM_SMEM>>>(
        xn2, w1h, b1, nullptr, nullptr, hbuf, MLPD, DD);
    // 8. MLP2 + residual -> out fp32
    gemm_f16k<false,true,false><<<dim3(DD/GN, BT/GM), 256, GEMM_SMEM>>>(
        hbuf, w2h, b2, x2, out, nullptr, DD, MLPD);
}

// round 5
// speedup vs baseline: 7.2670x; 1.0568x over previous
#include <cuda_runtime.h>
#include <cuda_fp16.h>
#include <math.h>
#include <stdint.h>

// ---------------- problem constants ----------------
#define BB 2
#define TT 2048
#define DD 1024
#define HH 16
#define HD 64
#define STRIDE 8
#define MLPD 4096
#define BT (BB*TT)          // 4096 rows
#define D3 (3*DD)           // 3072

// ---------------- scratch buffers (static device memory) ----------------
__device__ __half g_xn [BT*DD];
__device__ __half g_o  [BT*DD];
__device__ __half g_xn2[BT*DD];
__device__ __half g_h  [BT*MLPD];
__device__ __half g_win[D3*DD];
__device__ __half g_wout[DD*DD];
__device__ __half g_w1 [MLPD*DD];
__device__ __half g_w2 [DD*MLPD];
__device__ __half g_qkv[BT*D3];     // fp16 qkv
__device__ float g_x2 [BT*DD];

// ---------------- helpers ----------------
__device__ __forceinline__ uint32_t smem_u32(const void* p) {
    uint32_t a;
    asm("{ .reg .u64 t; cvta.to.shared.u64 t, %1; cvt.u32.u64 %0, t; }" : "=r"(a) : "l"(p));
    return a;
}
__device__ __forceinline__ void cp16(uint32_t dst, const void* src) {
    asm volatile("cp.async.cg.shared.global [%0], [%1], 16;" :: "r"(dst), "l"(src) : "memory");
}
__device__ __forceinline__ void ldmx4(uint32_t* r, uint32_t addr) {
    asm volatile("ldmatrix.sync.aligned.m8n8.x4.shared.b16 {%0,%1,%2,%3}, [%4];"
        : "=r"(r[0]), "=r"(r[1]), "=r"(r[2]), "=r"(r[3]) : "r"(addr));
}
__device__ __forceinline__ void mma_f16(float* c, const uint32_t* a, const uint32_t* b) {
    asm volatile("mma.sync.aligned.m16n8k16.row.col.f32.f16.f16.f32 "
        "{%0,%1,%2,%3}, {%4,%5,%6,%7}, {%8,%9}, {%0,%1,%2,%3};"
        : "+f"(c[0]), "+f"(c[1]), "+f"(c[2]), "+f"(c[3])
        : "r"(a[0]), "r"(a[1]), "r"(a[2]), "r"(a[3]), "r"(b[0]), "r"(b[1]));
}
// XOR swizzle for 64B rows, 16B chunks: conflict-free for ldmatrix & stores
__device__ __forceinline__ uint32_t swz(int r, int c) {
    return (uint32_t)((c ^ (r & 3) ^ ((r >> 2) & 1)) & 3);
}

// ---------------- fp16 HMMA GEMM: C[M,N] = A @ W^T (+bias)(+gelu)(+res) ----
// CTA tile 128x128, GK=32, 4-stage cp.async, 4 warps (2x2, warp tile 64x64).
#define GM 128
#define GN 128
#define GK 32
#define STAGE_B 16384               // A 8KB + W 8KB
#define NST 4
#define GEMM_SMEM (NST*STAGE_B)     // 65536

template<bool GELU_, bool RES_, bool F16O_>
__global__ void __launch_bounds__(128, 2) gemm_f16k(
    const __half* __restrict__ A, const __half* __restrict__ W,
    const float* __restrict__ bias, const float* __restrict__ Rres,
    float* __restrict__ C, __half* __restrict__ Cf, int N, int K)
{
    extern __shared__ char smem[];
    const uint32_t sb = smem_u32(smem);
    const int t = threadIdx.x;
    const int wid = t >> 5, lane = t & 31;
    const int m0 = blockIdx.y * GM;
    const int n0 = blockIdx.x * GN;
    const int wm = (wid & 1) * 64;
    const int wn = (wid >> 1) * 64;

    const int nch = K / GK;

    auto load_stage = [&](int chunk, int s) {
        const uint32_t base = sb + s * STAGE_B;
        #pragma unroll
        for (int j = 0; j < 4; j++) {
            const int c = t + j * 128;              // 512 chunks per 8KB tile
            const int r = c >> 2, col = c & 3;
            const uint32_t so = (uint32_t)(r * 64 + swz(r, col) * 16);
            const size_t k0 = (size_t)chunk * GK + col * 8;
            cp16(base + so,        A + (size_t)(m0 + r) * K + k0);
            cp16(base + 8192 + so, W + (size_t)(n0 + r) * K + k0);
        }
    };

    float acc[4][8][4];
    #pragma unroll
    for (int i = 0; i < 4; i++)
        #pragma unroll
        for (int j = 0; j < 8; j++)
            #pragma unroll
            for (int k = 0; k < 4; k++) acc[i][j][k] = 0.f;

    load_stage(0, 0); asm volatile("cp.async.commit_group;" ::: "memory");
    load_stage(1, 1); asm volatile("cp.async.commit_group;" ::: "memory");
    load_stage(2, 2); asm volatile("cp.async.commit_group;" ::: "memory");

    // ldmatrix lane addressing
    const int la_row = lane & 15;            // A: rows 0-15, lanes 16-31 -> k half 1
    const int la_kh  = lane >> 4;
    const int lb_row = (lane & 7) + ((lane >> 4) << 3);  // B: two n8 tiles
    const int lb_kh  = (lane >> 3) & 1;

    for (int i = 0; i < nch; i++) {
        asm volatile("cp.async.wait_group 2;" ::: "memory");
        __syncthreads();
        if (i + 3 < nch) load_stage(i + 3, (i + 3) & 3);
        asm volatile("cp.async.commit_group;" ::: "memory");

        const uint32_t aB = sb + (i & 3) * STAGE_B;
        const uint32_t wB = aB + 8192;

        #pragma unroll
        for (int kk = 0; kk < 2; kk++) {
            uint32_t b4[4][4];
            #pragma unroll
            for (int nf2 = 0; nf2 < 4; nf2++) {
                const int r = wn + nf2 * 16 + lb_row;
                const int c = kk * 2 + lb_kh;
                ldmx4(b4[nf2], wB + (uint32_t)(r * 64) + swz(r, c) * 16);
            }
            #pragma unroll
            for (int mf = 0; mf < 4; mf++) {
                uint32_t a[4];
                const int r = wm + mf * 16 + la_row;
                const int c = kk * 2 + la_kh;
                ldmx4(a, aB + (uint32_t)(r * 64) + swz(r, c) * 16);
                #pragma unroll
                for (int nf2 = 0; nf2 < 4; nf2++) {
                    mma_f16(acc[mf][2 * nf2 + 0], a, &b4[nf2][0]);
                    mma_f16(acc[mf][2 * nf2 + 1], a, &b4[nf2][2]);
                }
            }
        }
    }

    // ---- epilogue: registers -> gmem
    const int er = lane >> 2;
    const int ec = (lane & 3) * 2;
    #pragma unroll
    for (int mf = 0; mf < 4; mf++) {
        #pragma unroll
        for (int nf = 0; nf < 8; nf++) {
            const int c0 = n0 + wn + nf * 8 + ec;
            const float b0 = bias[c0], b1 = bias[c0 + 1];
            #pragma unroll
            for (int half = 0; half < 2; half++) {
                const int r = m0 + wm + mf * 16 + er + half * 8;
                float v0 = acc[mf][nf][half * 2 + 0] + b0;
                float v1 = acc[mf][nf][half * 2 + 1] + b1;
                if (GELU_) {
                    v0 = 0.5f * v0 * (1.0f + erff(v0 * 0.70710678118654752f));
                    v1 = 0.5f * v1 * (1.0f + erff(v1 * 0.70710678118654752f));
                }
                if (RES_) {
                    v0 += Rres[(size_t)r * N + c0];
                    v1 += Rres[(size_t)r * N + c0 + 1];
                }
                if (F16O_) {
                    *(__half2*)(Cf + (size_t)r * N + c0) = __floats2half2_rn(v0, v1);
                } else {
                    float2 p; p.x = v0; p.y = v1;
                    *(float2*)(C + (size_t)r * N + c0) = p;
                }
            }
        }
    }
}

// ---------------- LayerNorm -> f16 ----------------
__global__ __launch_bounds__(256) void ln_f16_kernel(
    const float* __restrict__ x, const float* __restrict__ g, const float* __restrict__ b,
    __half* __restrict__ y)
{
    const int row = blockIdx.x;
    const int tid = threadIdx.x;
    float4 v = ((const float4*)(x + (size_t)row * DD))[tid];

    float s  = v.x + v.y + v.z + v.w;
    float sq = v.x*v.x + v.y*v.y + v.z*v.z + v.w*v.w;
    __shared__ float red_s[8], red_q[8];
    for (int o = 16; o > 0; o >>= 1) {
        s  += __shfl_xor_sync(0xffffffffu, s,  o);
        sq += __shfl_xor_sync(0xffffffffu, sq, o);
    }
    const int wid = tid >> 5, lid = tid & 31;
    if (lid == 0) { red_s[wid] = s; red_q[wid] = sq; }
    __syncthreads();
    if (tid == 0) {
        float ts = 0.f, tq = 0.f;
        #pragma unroll
        for (int i = 0; i < 8; i++) { ts += red_s[i]; tq += red_q[i]; }
        red_s[0] = ts * (1.0f / DD);
        red_q[0] = tq * (1.0f / DD);
    }
    __syncthreads();
    const float mean = red_s[0];
    const float rstd = rsqrtf(red_q[0] - mean * mean + 1e-5f);

    const float4 gg = ((const float4*)g)[tid];
    const float4 bb = ((const float4*)b)[tid];
    float o0 = (v.x - mean) * rstd * gg.x + bb.x;
    float o1 = (v.y - mean) * rstd * gg.y + bb.y;
    float o2 = (v.z - mean) * rstd * gg.z + bb.z;
    float o3 = (v.w - mean) * rstd * gg.w + bb.w;
    __half2* py = (__half2*)(y + (size_t)row * DD);
    py[2*tid]   = __floats2half2_rn(o0, o1);
    py[2*tid+1] = __floats2half2_rn(o2, o3);
}

// ---------------- fp32 -> fp16 convert (weights) ----------------
__global__ __launch_bounds__(256) void cvt_f16_kernel(
    const float* __restrict__ src, __half* __restrict__ dst, int n4)
{
    int i = blockIdx.x * 256 + threadIdx.x;
    if (i >= n4) return;
    float4 v = ((const float4*)src)[i];
    ((__half2*)dst)[2*i]   = __floats2half2_rn(v.x, v.y);
    ((__half2*)dst)[2*i+1] = __floats2half2_rn(v.z, v.w);
}

// ---------------- non-global rows: o = v (half -> half, 8 at a time) -------
__global__ __launch_bounds__(256) void copy_v_kernel(
    __half* __restrict__ o, const __half* __restrict__ qkv)
{
    const int idx = blockIdx.x * 256 + threadIdx.x;   // over BT*DD/8
    const int d8  = idx & (DD / 8 - 1);
    const int row = idx >> 7;
    const int tt  = row & (TT - 1);
    if ((tt & (STRIDE - 1)) != 0) {
        *(uint4*)(o + (size_t)row * DD + d8 * 8) =
            *(const uint4*)(qkv + (size_t)row * D3 + 2 * DD + d8 * 8);
    }
}

// ---------------- global rows: flash-style attention (half in, fp32 math) --
#define AQ 32
#define CK 128
#define KPAD 68
#define ATTN_SMEM (AQ*64*4 + CK*KPAD*4 + CK*64*4 + 8*4*CK*4)   // 92160

__global__ __launch_bounds__(256) void attn_flash_kernel(
    __half* __restrict__ o, const __half* __restrict__ qkv)
{
    extern __shared__ char smem[];
    float* Qs = (float*)smem;                         // [32][64]
    float* Ks = Qs + AQ * 64;                         // [128][68]
    float* Vs = Ks + CK * KPAD;                       // [128][64]
    float* Ps = Vs + CK * 64;                         // [8][4][128]

    const int t = threadIdx.x;
    const int wid = t >> 5, lane = t & 31;
    const int blk = blockIdx.x;
    const int qt = blk & 7;
    const int h  = (blk >> 3) & (HH - 1);
    const int b  = blk >> 7;

    // load Q tile (32 queries), pre-scaled by 1/sqrt(64)
    {
        const int j = t >> 3, c = t & 7;              // 256 thr = 32 q x 8 chunks
        const int tq = (qt * AQ + j) * STRIDE;
        uint4 raw = *(const uint4*)(qkv + (size_t)(b * TT + tq) * D3 + h * HD + c * 8);
        const __half2* hp = (const __half2*)&raw;
        float* dst = Qs + j * 64 + c * 8;
        #pragma unroll
        for (int u = 0; u < 4; u++) {
            float2 f = __half22float2(hp[u]);
            dst[2*u]   = f.x * 0.125f;
            dst[2*u+1] = f.y * 0.125f;
        }
    }

    float m[4], l[4], oa[4][2];
    #pragma unroll
    for (int q = 0; q < 4; q++) {
        m[q] = -1e30f; l[q] = 0.f; oa[q][0] = 0.f; oa[q][1] = 0.f;
    }

    for (int ch = 0; ch < TT / CK; ch++) {
        const int k0 = ch * CK;
        // load K, V chunk (half -> fp32 smem)
        #pragma unroll
        for (int it = 0; it < 4; it++) {
            const int idx = t + it * 256;             // 1024 uint4 per tensor
            const int kk = idx >> 3, c = idx & 7;
            const size_t rb = (size_t)(b * TT + k0 + kk) * D3 + h * HD + c * 8;
            uint4 kraw = *(const uint4*)(qkv + DD + rb);
            uint4 vraw = *(const uint4*)(qkv + 2 * DD + rb);
            const __half2* kp = (const __half2*)&kraw;
            const __half2* vp = (const __half2*)&vraw;
            float* kd = Ks + kk * KPAD + c * 8;
            float* vd = Vs + kk * 64   + c * 8;
            #pragma unroll
            for (int u = 0; u < 4; u++) {
                float2 kf = __half22float2(kp[u]);
                float2 vf = __half22float2(vp[u]);
                kd[2*u] = kf.x; kd[2*u+1] = kf.y;
                vd[2*u] = vf.x; vd[2*u+1] = vf.y;
            }
        }
        __syncthreads();

        // scores
        float s[4][4];
        #pragma unroll
        for (int q = 0; q < 4; q++)
            #pragma unroll
            for (int jj = 0; jj < 4; jj++) s[q][jj] = 0.f;
        const float* qrow = Qs + (wid * 4) * 64;
        #pragma unroll 4
        for (int d4 = 0; d4 < 64; d4 += 4) {
            float4 kv[4];
            #pragma unroll
            for (int jj = 0; jj < 4; jj++)
                kv[jj] = *(const float4*)(Ks + (lane + 32 * jj) * KPAD + d4);
            #pragma unroll
            for (int q = 0; q < 4; q++) {
                float4 qv = *(const float4*)(qrow + q * 64 + d4);
                #pragma unroll
                for (int jj = 0; jj < 4; jj++) {
                    s[q][jj] += qv.x * kv[jj].x + qv.y * kv[jj].y
                              + qv.z * kv[jj].z + qv.w * kv[jj].w;
                }
            }
        }

        // online softmax per query
        #pragma unroll
        for (int q = 0; q < 4; q++) {
            float cm = fmaxf(fmaxf(s[q][0], s[q][1]), fmaxf(s[q][2], s[q][3]));
            for (int off = 16; off > 0; off >>= 1)
                cm = fmaxf(cm, __shfl_xor_sync(0xffffffffu, cm, off));
            const float mnew = fmaxf(m[q], cm);
            const float corr = expf(m[q] - mnew);
            float e0 = expf(s[q][0] - mnew), e1 = expf(s[q][1] - mnew);
            float e2 = expf(s[q][2] - mnew), e3 = expf(s[q][3] - mnew);
            float ls = e0 + e1 + e2 + e3;
            for (int off = 16; off > 0; off >>= 1)
                ls += __shfl_xor_sync(0xffffffffu, ls, off);
            l[q] = l[q] * corr + ls;
            m[q] = mnew;
            oa[q][0] *= corr; oa[q][1] *= corr;
            float* pp = Ps + (wid * 4 + q) * CK;
            pp[lane]      = e0;
            pp[lane + 32] = e1;
            pp[lane + 64] = e2;
            pp[lane + 96] = e3;
        }
        __syncwarp();

        // PV
        #pragma unroll 4
        for (int k = 0; k < CK; k++) {
            const float v0 = Vs[k * 64 + lane];
            const float v1 = Vs[k * 64 + lane + 32];
            #pragma unroll
            for (int q = 0; q < 4; q++) {
                const float p = Ps[(wid * 4 + q) * CK + k];
                oa[q][0] += p * v0;
                oa[q][1] += p * v1;
            }
        }
        __syncthreads();
    }

    #pragma unroll
    for (int q = 0; q < 4; q++) {
        const float inv = 1.0f / l[q];
        const int tq = (qt * AQ + wid * 4 + q) * STRIDE;
        const size_t base = (size_t)(b * TT + tq) * DD + h * HD;
        o[base + lane]      = __float2half(oa[q][0] * inv);
        o[base + lane + 32] = __float2half(oa[q][1] * inv);
    }
}

// ---------------- launch ----------------
extern "C" void kernel_launch(void* const* d_in, const int* in_sizes, int n_in,
                              void* d_out, int out_size)
{
    const float* x     = (const float*)d_in[0];
    const float* w_in  = (const float*)d_in[1];
    const float* b_in  = (const float*)d_in[2];
    const float* w_out = (const float*)d_in[3];
    const float* b_out = (const float*)d_in[4];
    const float* w1    = (const float*)d_in[5];
    const float* b1    = (const float*)d_in[6];
    const float* w2    = (const float*)d_in[7];
    const float* b2    = (const float*)d_in[8];
    const float* ln1_g = (const float*)d_in[9];
    const float* ln1_b = (const float*)d_in[10];
    const float* ln2_g = (const float*)d_in[11];
    const float* ln2_b = (const float*)d_in[12];
    float* out = (float*)d_out;

    __half *xn,*o,*xn2,*hbuf,*win,*wout,*w1h,*w2h,*qkv;
    float *x2;
    cudaGetSymbolAddress((void**)&xn,   g_xn);
    cudaGetSymbolAddress((void**)&o,    g_o);
    cudaGetSymbolAddress((void**)&xn2,  g_xn2);
    cudaGetSymbolAddress((void**)&hbuf, g_h);
    cudaGetSymbolAddress((void**)&win,  g_win);
    cudaGetSymbolAddress((void**)&wout, g_wout);
    cudaGetSymbolAddress((void**)&w1h,  g_w1);
    cudaGetSymbolAddress((void**)&w2h,  g_w2);
    cudaGetSymbolAddress((void**)&qkv,  g_qkv);
    cudaGetSymbolAddress((void**)&x2,   g_x2);

    cudaFuncSetAttribute(gemm_f16k<false,false,true >, cudaFuncAttributeMaxDynamicSharedMemorySize, GEMM_SMEM);
    cudaFuncSetAttribute(gemm_f16k<false,true ,false>, cudaFuncAttributeMaxDynamicSharedMemorySize, GEMM_SMEM);
    cudaFuncSetAttribute(gemm_f16k<true ,false,true >, cudaFuncAttributeMaxDynamicSharedMemorySize, GEMM_SMEM);
    cudaFuncSetAttribute(attn_flash_kernel, cudaFuncAttributeMaxDynamicSharedMemorySize, ATTN_SMEM);

    // 1. LN1 -> f16
    ln_f16_kernel<<<BT, 256>>>(x, ln1_g, ln1_b, xn);
    // 2. convert weights -> f16
    cvt_f16_kernel<<<(D3*DD/4 + 255)/256, 256>>>(w_in,  win,  D3*DD/4);
    cvt_f16_kernel<<<(DD*DD/4 + 255)/256, 256>>>(w_out, wout, DD*DD/4);
    cvt_f16_kernel<<<(MLPD*DD/4 + 255)/256, 256>>>(w1,  w1h,  MLPD*DD/4);
    cvt_f16_kernel<<<(DD*MLPD/4 + 255)/256, 256>>>(w2,  w2h,  DD*MLPD/4);
    // 3. QKV GEMM -> f16 qkv
    gemm_f16k<false,false,true><<<dim3(D3/GN, BT/GM), 128, GEMM_SMEM>>>(
        xn, win, b_in, nullptr, nullptr, qkv, D3, DD);
    // 4. attention
    copy_v_kernel<<<(BT*DD/8)/256, 256>>>(o, qkv);
    attn_flash_kernel<<<BB*HH*8, 256, ATTN_SMEM>>>(o, qkv);
    // 5. out-proj + residual -> x2 fp32
    gemm_f16k<false,true,false><<<dim3(DD/GN, BT/GM), 128, GEMM_SMEM>>>(
        o, wout, b_out, x, x2, nullptr, DD, DD);
    // 6. LN2 -> f16
    ln_f16_kernel<<<BT, 256>>>(x2, ln2_g, ln2_b, xn2);
    // 7. MLP1 + GELU -> h f16
    gemm_f16k<true,false,true><<<dim3(MLPD/GN, BT/GM), 128, GEMM_SMEM>>>(
        xn2, w1h, b1, nullptr, nullptr, hbuf, MLPD, DD);
    // 8. MLP2 + residual -> out fp32
    gemm_f16k<false,true,false><<<dim3(DD/GN, BT/GM), 128, GEMM_SMEM>>>(
        hbuf, w2h, b2, x2, out, nullptr, DD, MLPD);
}

// round 7
// speedup vs baseline: 8.1700x; 1.1243x over previous
#include <cuda_runtime.h>
#include <cuda_fp16.h>
#include <math.h>
#include <stdint.h>

// ---------------- problem constants ----------------
#define BB 2
#define TT 2048
#define DD 1024
#define HH 16
#define HD 64
#define STRIDE 8
#define MLPD 4096
#define BT (BB*TT)          // 4096 rows
#define D3 (3*DD)           // 3072

// ---------------- scratch buffers ----------------
__device__ __half g_xn [BT*DD];
__device__ __half g_o  [BT*DD];
__device__ __half g_xn2[BT*DD];
__device__ __half g_h  [BT*MLPD];
__device__ __half g_win[D3*DD];
__device__ __half g_wout[DD*DD];
__device__ __half g_w1 [MLPD*DD];
__device__ __half g_w2 [DD*MLPD];
__device__ __half g_qkv[BT*D3];
__device__ float g_x2 [BT*DD];

// ---------------- helpers ----------------
__device__ __forceinline__ uint32_t smem_u32(const void* p) {
    uint32_t a;
    asm("{ .reg .u64 t; cvta.to.shared.u64 t, %1; cvt.u32.u64 %0, t; }" : "=r"(a) : "l"(p));
    return a;
}
__device__ __forceinline__ void cp16(uint32_t dst, const void* src) {
    asm volatile("cp.async.cg.shared.global [%0], [%1], 16;" :: "r"(dst), "l"(src) : "memory");
}
__device__ __forceinline__ void ldmx4(uint32_t* r, uint32_t addr) {
    asm volatile("ldmatrix.sync.aligned.m8n8.x4.shared.b16 {%0,%1,%2,%3}, [%4];"
        : "=r"(r[0]), "=r"(r[1]), "=r"(r[2]), "=r"(r[3]) : "r"(addr));
}
__device__ __forceinline__ void ldmx4t(uint32_t* r, uint32_t addr) {
    asm volatile("ldmatrix.sync.aligned.m8n8.x4.trans.shared.b16 {%0,%1,%2,%3}, [%4];"
        : "=r"(r[0]), "=r"(r[1]), "=r"(r[2]), "=r"(r[3]) : "r"(addr));
}
__device__ __forceinline__ void mma_f16(float* c, const uint32_t* a, const uint32_t* b) {
    asm volatile("mma.sync.aligned.m16n8k16.row.col.f32.f16.f16.f32 "
        "{%0,%1,%2,%3}, {%4,%5,%6,%7}, {%8,%9}, {%0,%1,%2,%3};"
        : "+f"(c[0]), "+f"(c[1]), "+f"(c[2]), "+f"(c[3])
        : "r"(a[0]), "r"(a[1]), "r"(a[2]), "r"(a[3]), "r"(b[0]), "r"(b[1]));
}
__device__ __forceinline__ uint32_t swz(int r, int c) {
    return (uint32_t)((c ^ (r & 3) ^ ((r >> 2) & 1)) & 3);
}

// ---------------- fp16 HMMA GEMM: C[M,N] = A @ W^T (+bias)(+gelu)(+res) ----
// CTA tile 128x256, GK=32, 5-stage cp.async, 8 warps (2M x 4N, warp 64x64).
#define GM 128
#define GN 256
#define GK 32
#define STAGE_B 24576               // A 8KB + W 16KB
#define NST 5
#define GEMM_SMEM (NST*STAGE_B)     // 122880

template<bool GELU_, bool RES_, bool F16O_>
__global__ void __launch_bounds__(256, 1) gemm_f16k(
    const __half* __restrict__ A, const __half* __restrict__ W,
    const float* __restrict__ bias, const float* __restrict__ Rres,
    float* __restrict__ C, __half* __restrict__ Cf, int N, int K)
{
    extern __shared__ char smem[];
    const uint32_t sb = smem_u32(smem);
    const int t = threadIdx.x;
    const int wid = t >> 5, lane = t & 31;
    const int m0 = blockIdx.y * GM;
    const int n0 = blockIdx.x * GN;
    const int wm = (wid & 1) * 64;
    const int wn = (wid >> 1) * 64;

    const int nch = K / GK;

    auto load_stage = [&](int chunk, int s) {
        const uint32_t base = sb + s * STAGE_B;
        // A tile: 128 rows x 32k = 512 chunks of 16B
        #pragma unroll
        for (int j = 0; j < 2; j++) {
            const int c = t + j * 256;
            const int r = c >> 2, col = c & 3;
            const uint32_t so = (uint32_t)(r * 64 + swz(r, col) * 16);
            cp16(base + so, A + (size_t)(m0 + r) * K + (size_t)chunk * GK + col * 8);
        }
        // W tile: 256 rows x 32k = 1024 chunks
        #pragma unroll
        for (int j = 0; j < 4; j++) {
            const int c = t + j * 256;
            const int r = c >> 2, col = c & 3;
            const uint32_t so = (uint32_t)(r * 64 + swz(r, col) * 16);
            cp16(base + 8192 + so, W + (size_t)(n0 + r) * K + (size_t)chunk * GK + col * 8);
        }
        asm volatile("cp.async.commit_group;" ::: "memory");
    };

    float acc[4][8][4];
    #pragma unroll
    for (int i = 0; i < 4; i++)
        #pragma unroll
        for (int j = 0; j < 8; j++)
            #pragma unroll
            for (int k = 0; k < 4; k++) acc[i][j][k] = 0.f;

    load_stage(0, 0);
    load_stage(1, 1);
    load_stage(2, 2);
    load_stage(3, 3);

    const int la_row = lane & 15;
    const int la_kh  = lane >> 4;
    const int lb_row = (lane & 7) + ((lane >> 4) << 3);
    const int lb_kh  = (lane >> 3) & 1;

    for (int i = 0; i < nch; i++) {
        asm volatile("cp.async.wait_group 3;" ::: "memory");
        __syncthreads();
        if (i + 4 < nch) load_stage(i + 4, (i + 4) % NST);

        const uint32_t aB = sb + (i % NST) * STAGE_B;
        const uint32_t wB = aB + 8192;

        #pragma unroll
        for (int kk = 0; kk < 2; kk++) {
            uint32_t b4[4][4];
            #pragma unroll
            for (int nf2 = 0; nf2 < 4; nf2++) {
                const int r = wn + nf2 * 16 + lb_row;
                const int c = kk * 2 + lb_kh;
                ldmx4(b4[nf2], wB + (uint32_t)(r * 64) + swz(r, c) * 16);
            }
            #pragma unroll
            for (int mf = 0; mf < 4; mf++) {
                uint32_t a[4];
                const int r = wm + mf * 16 + la_row;
                const int c = kk * 2 + la_kh;
                ldmx4(a, aB + (uint32_t)(r * 64) + swz(r, c) * 16);
                #pragma unroll
                for (int nf2 = 0; nf2 < 4; nf2++) {
                    mma_f16(acc[mf][2 * nf2 + 0], a, &b4[nf2][0]);
                    mma_f16(acc[mf][2 * nf2 + 1], a, &b4[nf2][2]);
                }
            }
        }
    }

    // ---- epilogue
    const int er = lane >> 2;
    const int ec = (lane & 3) * 2;
    #pragma unroll
    for (int mf = 0; mf < 4; mf++) {
        #pragma unroll
        for (int nf = 0; nf < 8; nf++) {
            const int c0 = n0 + wn + nf * 8 + ec;
            const float b0 = bias[c0], b1 = bias[c0 + 1];
            #pragma unroll
            for (int half = 0; half < 2; half++) {
                const int r = m0 + wm + mf * 16 + er + half * 8;
                float v0 = acc[mf][nf][half * 2 + 0] + b0;
                float v1 = acc[mf][nf][half * 2 + 1] + b1;
                if (GELU_) {
                    v0 = 0.5f * v0 * (1.0f + erff(v0 * 0.70710678118654752f));
                    v1 = 0.5f * v1 * (1.0f + erff(v1 * 0.70710678118654752f));
                }
                if (RES_) {
                    v0 += Rres[(size_t)r * N + c0];
                    v1 += Rres[(size_t)r * N + c0 + 1];
                }
                if (F16O_) {
                    *(__half2*)(Cf + (size_t)r * N + c0) = __floats2half2_rn(v0, v1);
                } else {
                    float2 p; p.x = v0; p.y = v1;
                    *(float2*)(C + (size_t)r * N + c0) = p;
                }
            }
        }
    }
}

// ---------------- LayerNorm -> f16 ----------------
__global__ __launch_bounds__(256) void ln_f16_kernel(
    const float* __restrict__ x, const float* __restrict__ g, const float* __restrict__ b,
    __half* __restrict__ y)
{
    const int row = blockIdx.x;
    const int tid = threadIdx.x;
    float4 v = ((const float4*)(x + (size_t)row * DD))[tid];

    float s  = v.x + v.y + v.z + v.w;
    float sq = v.x*v.x + v.y*v.y + v.z*v.z + v.w*v.w;
    __shared__ float red_s[8], red_q[8];
    for (int o = 16; o > 0; o >>= 1) {
        s  += __shfl_xor_sync(0xffffffffu, s,  o);
        sq += __shfl_xor_sync(0xffffffffu, sq, o);
    }
    const int wid = tid >> 5, lid = tid & 31;
    if (lid == 0) { red_s[wid] = s; red_q[wid] = sq; }
    __syncthreads();
    if (tid == 0) {
        float ts = 0.f, tq = 0.f;
        #pragma unroll
        for (int i = 0; i < 8; i++) { ts += red_s[i]; tq += red_q[i]; }
        red_s[0] = ts * (1.0f / DD);
        red_q[0] = tq * (1.0f / DD);
    }
    __syncthreads();
    const float mean = red_s[0];
    const float rstd = rsqrtf(red_q[0] - mean * mean + 1e-5f);

    const float4 gg = ((const float4*)g)[tid];
    const float4 bb = ((const float4*)b)[tid];
    float o0 = (v.x - mean) * rstd * gg.x + bb.x;
    float o1 = (v.y - mean) * rstd * gg.y + bb.y;
    float o2 = (v.z - mean) * rstd * gg.z + bb.z;
    float o3 = (v.w - mean) * rstd * gg.w + bb.w;
    __half2* py = (__half2*)(y + (size_t)row * DD);
    py[2*tid]   = __floats2half2_rn(o0, o1);
    py[2*tid+1] = __floats2half2_rn(o2, o3);
}

// ---------------- fused fp32 -> fp16 weight convert ----------------
#define CV0 (D3*DD/4)
#define CV1 (DD*DD/4)
#define CV2 (MLPD*DD/4)
#define CV3 (DD*MLPD/4)
__global__ __launch_bounds__(256) void cvt_all_kernel(
    const float* __restrict__ s0, __half* __restrict__ d0,
    const float* __restrict__ s1, __half* __restrict__ d1,
    const float* __restrict__ s2, __half* __restrict__ d2,
    const float* __restrict__ s3, __half* __restrict__ d3)
{
    int i = blockIdx.x * 256 + threadIdx.x;
    const float* src; __half* dst;
    if (i < CV0)                       { src = s0; dst = d0; }
    else if ((i -= CV0) < CV1)         { src = s1; dst = d1; }
    else if ((i -= CV1) < CV2)         { src = s2; dst = d2; }
    else if ((i -= CV2) < CV3)         { src = s3; dst = d3; }
    else return;
    float4 v = ((const float4*)src)[i];
    ((__half2*)dst)[2*i]   = __floats2half2_rn(v.x, v.y);
    ((__half2*)dst)[2*i+1] = __floats2half2_rn(v.z, v.w);
}

// ---------------- non-global rows: o = v ----------------
__global__ __launch_bounds__(256) void copy_v_kernel(
    __half* __restrict__ o, const __half* __restrict__ qkv)
{
    const int idx = blockIdx.x * 256 + threadIdx.x;
    const int d8  = idx & (DD / 8 - 1);
    const int row = idx >> 7;
    const int tt  = row & (TT - 1);
    if ((tt & (STRIDE - 1)) != 0) {
        *(uint4*)(o + (size_t)row * DD + d8 * 8) =
            *(const uint4*)(qkv + (size_t)row * D3 + 2 * DD + d8 * 8);
    }
}

// ---------------- global rows: HMMA flash attention ----------------
// Block: 128 thr (4 warps), 32 queries. Key chunks of 128, double-buffered.
#define AQ 32
#define CK 128
#define KVST 72                       // halfs per row (64 + 8 pad) = 144B
#define SS_ST 132                     // floats per Ss row
#define PS_ST 136                     // halfs per Ps row = 272B
#define QS_OFF 0
#define KS_OFF 4608                   // 32*144
#define VS_OFF (KS_OFF + 2*CK*144)   // 41472
#define SS_OFF (VS_OFF + 2*CK*144)   // 78336
#define PS_OFF (SS_OFF + AQ*SS_ST*4) // 95232
#define ML_OFF (PS_OFF + AQ*PS_ST*2) // 103936
#define ATTN_SMEM (ML_OFF + 3*AQ*4)  // 104320

__global__ void __launch_bounds__(128, 2) attn_hmma_kernel(
    __half* __restrict__ o, const __half* __restrict__ qkv)
{
    extern __shared__ char smem[];
    const uint32_t sb = smem_u32(smem);
    float* Ss = (float*)(smem + SS_OFF);
    float* m_s = (float*)(smem + ML_OFF);
    float* l_s = m_s + AQ;
    float* corr_s = l_s + AQ;

    const int t = threadIdx.x;
    const int w = t >> 5, lane = t & 31;
    const int blk = blockIdx.x;
    const int qt = blk & 7;
    const int h  = (blk >> 3) & (HH - 1);
    const int b  = blk >> 7;

    // ---- load Q tile (32 queries x 64), scaled by 0.125 (exact in fp16)
    {
        const __half2 sc = __floats2half2_rn(0.125f, 0.125f);
        #pragma unroll
        for (int j = 0; j < 2; j++) {
            const int idx = t + j * 128;          // 256 uint4
            const int q = idx >> 3, c = idx & 7;
            const int tq = (qt * AQ + q) * STRIDE;
            uint4 raw = *(const uint4*)(qkv + (size_t)(b * TT + tq) * D3 + h * HD + c * 8);
            __half2* hp = (__half2*)&raw;
            #pragma unroll
            for (int u = 0; u < 4; u++) hp[u] = __hmul2(hp[u], sc);
            *(uint4*)(smem + QS_OFF + q * 144 + c * 16) = raw;
        }
    }
    if (t < AQ) { m_s[t] = -1e30f; l_s[t] = 0.f; }
    __syncthreads();

    // ---- preload Q fragments (m strip = (w&1)*16, k = 64 dims -> 4 ksteps)
    uint32_t aq[4][4];
    {
        const int r = (w & 1) * 16 + (lane & 15);
        #pragma unroll
        for (int ks = 0; ks < 4; ks++)
            ldmx4(aq[ks], sb + QS_OFF + (uint32_t)(r * 144) + (ks * 2 + (lane >> 4)) * 16);
    }

    // ---- K/V chunk loader (cp.async, 16 chunks of 128 keys)
    auto load_kv = [&](int chunk, int s) {
        const int k0 = chunk * CK;
        const uint32_t kb = sb + KS_OFF + s * (CK * 144);
        const uint32_t vb = sb + VS_OFF + s * (CK * 144);
        #pragma unroll
        for (int j = 0; j < 8; j++) {
            const int idx = t + j * 128;          // 1024 chunks per tensor
            const int r = idx >> 3, c = idx & 7;
            const size_t g = (size_t)(b * TT + k0 + r) * D3 + h * HD + c * 8;
            cp16(kb + r * 144 + c * 16, qkv + DD + g);
            cp16(vb + r * 144 + c * 16, qkv + 2 * DD + g);
        }
        asm volatile("cp.async.commit_group;" ::: "memory");
    };

    float oacc[4][4];
    #pragma unroll
    for (int i = 0; i < 4; i++)
        #pragma unroll
        for (int j = 0; j < 4; j++) oacc[i][j] = 0.f;

    load_kv(0, 0);

    const int lb_row = (lane & 7) + ((lane >> 4) << 3);
    const int lb_kh  = (lane >> 3) & 1;

    for (int ch = 0; ch < TT / CK; ch++) {
        if (ch + 1 < TT / CK) load_kv(ch + 1, (ch + 1) & 1);
        asm volatile("cp.async.wait_group 1;" ::: "memory");
        __syncthreads();
        const uint32_t kB = sb + KS_OFF + (ch & 1) * (CK * 144);
        const uint32_t vB = sb + VS_OFF + (ch & 1) * (CK * 144);

        // ---- S = Q K^T  (warp: m16 strip (w&1), n64 strip (w>>1))
        float sacc[8][4];
        #pragma unroll
        for (int i = 0; i < 8; i++)
            #pragma unroll
            for (int j = 0; j < 4; j++) sacc[i][j] = 0.f;
        #pragma unroll
        for (int ks = 0; ks < 4; ks++) {
            uint32_t b4[4][4];
            #pragma unroll
            for (int nf2 = 0; nf2 < 4; nf2++) {
                const int r = (w >> 1) * 64 + nf2 * 16 + lb_row;
                ldmx4(b4[nf2], kB + (uint32_t)(r * 144) + (ks * 2 + lb_kh) * 16);
            }
            #pragma unroll
            for (int nf2 = 0; nf2 < 4; nf2++) {
                mma_f16(sacc[2 * nf2 + 0], aq[ks], &b4[nf2][0]);
                mma_f16(sacc[2 * nf2 + 1], aq[ks], &b4[nf2][2]);
            }
        }
        // write S fragments -> Ss
        {
            const int row0 = (w & 1) * 16 + (lane >> 2);
            #pragma unroll
            for (int nf = 0; nf < 8; nf++) {
                const int col = (w >> 1) * 64 + nf * 8 + (lane & 3) * 2;
                Ss[row0 * SS_ST + col]       = sacc[nf][0];
                Ss[row0 * SS_ST + col + 1]   = sacc[nf][1];
                Ss[(row0 + 8) * SS_ST + col]     = sacc[nf][2];
                Ss[(row0 + 8) * SS_ST + col + 1] = sacc[nf][3];
            }
        }
        __syncthreads();

        // ---- online softmax: thread (q = t>>2, 32-key segment = (t&3)*32)
        {
            const int q = t >> 2;
            const int kseg = (t & 3) * 32;
            float4 sv[8];
            #pragma unroll
            for (int i = 0; i < 8; i++)
                sv[i] = *(float4*)(Ss + q * SS_ST + kseg + i * 4);
            float mx = -1e30f;
            #pragma unroll
            for (int i = 0; i < 8; i++)
                mx = fmaxf(mx, fmaxf(fmaxf(sv[i].x, sv[i].y), fmaxf(sv[i].z, sv[i].w)));
            mx = fmaxf(mx, __shfl_xor_sync(0xffffffffu, mx, 1));
            mx = fmaxf(mx, __shfl_xor_sync(0xffffffffu, mx, 2));
            const float m_old = m_s[q];
            const float mnew = fmaxf(m_old, mx);
            float lsum = 0.f;
            __half* pp = (__half*)(smem + PS_OFF) + q * PS_ST + kseg;
            #pragma unroll
            for (int i = 0; i < 8; i++) {
                float e0 = expf(sv[i].x - mnew), e1 = expf(sv[i].y - mnew);
                float e2 = expf(sv[i].z - mnew), e3 = expf(sv[i].w - mnew);
                lsum += e0 + e1 + e2 + e3;
                ((__half2*)(pp + i * 4))[0] = __floats2half2_rn(e0, e1);
                ((__half2*)(pp + i * 4))[1] = __floats2half2_rn(e2, e3);
            }
            lsum += __shfl_xor_sync(0xffffffffu, lsum, 1);
            lsum += __shfl_xor_sync(0xffffffffu, lsum, 2);
            if ((t & 3) == 0) {
                const float corr = expf(m_old - mnew);
                corr_s[q] = corr;
                l_s[q] = l_s[q] * corr + lsum;
                m_s[q] = mnew;
            }
        }
        __syncthreads();

        // ---- O = O*corr + P V  (warp: m16 strip (w&1), n32 strip (w>>1))
        {
            const int row0 = (w & 1) * 16 + (lane >> 2);
            const float c0 = corr_s[row0];
            const float c1 = corr_s[row0 + 8];
            #pragma unroll
            for (int nf = 0; nf < 4; nf++) {
                oacc[nf][0] *= c0; oacc[nf][1] *= c0;
                oacc[nf][2] *= c1; oacc[nf][3] *= c1;
            }
            const int arow = (w & 1) * 16 + (lane & 15);
            #pragma unroll
            for (int ks = 0; ks < 8; ks++) {
                uint32_t ap[4];
                ldmx4(ap, sb + PS_OFF + (uint32_t)(arow * 272) + (ks * 2 + (lane >> 4)) * 16);
                #pragma unroll
                for (int nf2 = 0; nf2 < 2; nf2++) {
                    uint32_t bv[4];
                    const int krow = ks * 16 + (lane & 7) + ((lane >> 3) & 1) * 8;
                    const int dcol = (w >> 1) * 32 + nf2 * 16 + (lane >> 4) * 8;
                    ldmx4t(bv, vB + (uint32_t)(krow * 144) + dcol * 2);
                    mma_f16(oacc[2 * nf2 + 0], ap, &bv[0]);
                    mma_f16(oacc[2 * nf2 + 1], ap, &bv[2]);
                }
            }
        }
        __syncthreads();
    }

    // ---- final: O / l, write out
    {
        const int row0 = (w & 1) * 16 + (lane >> 2);
        const float i0 = 1.0f / l_s[row0];
        const float i1 = 1.0f / l_s[row0 + 8];
        #pragma unroll
        for (int nf = 0; nf < 4; nf++) {
            const int d = (w >> 1) * 32 + nf * 8 + (lane & 3) * 2;
            const int tq0 = (qt * AQ + row0) * STRIDE;
            const int tq1 = (qt * AQ + row0 + 8) * STRIDE;
            *(__half2*)(o + (size_t)(b * TT + tq0) * DD + h * HD + d) =
                __floats2half2_rn(oacc[nf][0] * i0, oacc[nf][1] * i0);
            *(__half2*)(o + (size_t)(b * TT + tq1) * DD + h * HD + d) =
                __floats2half2_rn(oacc[nf][2] * i1, oacc[nf][3] * i1);
        }
    }
}

// ---------------- launch ----------------
extern "C" void kernel_launch(void* const* d_in, const int* in_sizes, int n_in,
                              void* d_out, int out_size)
{
    const float* x     = (const float*)d_in[0];
    const float* w_in  = (const float*)d_in[1];
    const float* b_in  = (const float*)d_in[2];
    const float* w_out = (const float*)d_in[3];
    const float* b_out = (const float*)d_in[4];
    const float* w1    = (const float*)d_in[5];
    const float* b1    = (const float*)d_in[6];
    const float* w2    = (const float*)d_in[7];
    const float* b2    = (const float*)d_in[8];
    const float* ln1_g = (const float*)d_in[9];
    const float* ln1_b = (const float*)d_in[10];
    const float* ln2_g = (const float*)d_in[11];
    const float* ln2_b = (const float*)d_in[12];
    float* out = (float*)d_out;

    __half *xn,*o,*xn2,*hbuf,*win,*wout,*w1h,*w2h,*qkv;
    float *x2;
    cudaGetSymbolAddress((void**)&xn,   g_xn);
    cudaGetSymbolAddress((void**)&o,    g_o);
    cudaGetSymbolAddress((void**)&xn2,  g_xn2);
    cudaGetSymbolAddress((void**)&hbuf, g_h);
    cudaGetSymbolAddress((void**)&win,  g_win);
    cudaGetSymbolAddress((void**)&wout, g_wout);
    cudaGetSymbolAddress((void**)&w1h,  g_w1);
    cudaGetSymbolAddress((void**)&w2h,  g_w2);
    cudaGetSymbolAddress((void**)&qkv,  g_qkv);
    cudaGetSymbolAddress((void**)&x2,   g_x2);

    cudaFuncSetAttribute(gemm_f16k<false,false,true >, cudaFuncAttributeMaxDynamicSharedMemorySize, GEMM_SMEM);
    cudaFuncSetAttribute(gemm_f16k<false,true ,false>, cudaFuncAttributeMaxDynamicSharedMemorySize, GEMM_SMEM);
    cudaFuncSetAttribute(gemm_f16k<true ,false,true >, cudaFuncAttributeMaxDynamicSharedMemorySize, GEMM_SMEM);
    cudaFuncSetAttribute(attn_hmma_kernel, cudaFuncAttributeMaxDynamicSharedMemorySize, ATTN_SMEM);

    // 1. LN1 -> f16
    ln_f16_kernel<<<BT, 256>>>(x, ln1_g, ln1_b, xn);
    // 2. convert all weights -> f16 (fused)
    cvt_all_kernel<<<(CV0 + CV1 + CV2 + CV3 + 255) / 256, 256>>>(
        w_in, win, w_out, wout, w1, w1h, w2, w2h);
    // 3. QKV GEMM -> f16 qkv
    gemm_f16k<false,false,true><<<dim3(D3/GN, BT/GM), 256, GEMM_SMEM>>>(
        xn, win, b_in, nullptr, nullptr, qkv, D3, DD);
    // 4. attention
    copy_v_kernel<<<(BT*DD/8)/256, 256>>>(o, qkv);
    attn_hmma_kernel<<<BB*HH*8, 128, ATTN_SMEM>>>(o, qkv);
    // 5. out-proj + residual -> x2 fp32
    gemm_f16k<false,true,false><<<dim3(DD/GN, BT/GM), 256, GEMM_SMEM>>>(
        o, wout, b_out, x, x2, nullptr, DD, DD);
    // 6. LN2 -> f16
    ln_f16_kernel<<<BT, 256>>>(x2, ln2_g, ln2_b, xn2);
    // 7. MLP1 + GELU -> h f16
    gemm_f16k<true,false,true><<<dim3(MLPD/GN, BT/GM), 256, GEMM_SMEM>>>(
        xn2, w1h, b1, nullptr, nullptr, hbuf, MLPD, DD);
    // 8. MLP2 + residual -> out fp32
    gemm_f16k<false,true,false><<<dim3(DD/GN, BT/GM), 256, GEMM_SMEM>>>(
        hbuf, w2h, b2, x2, out, nullptr, DD, MLPD);
}

// round 10
// speedup vs baseline: 9.9891x; 1.2226x over previous
#include <cuda_runtime.h>
#include <cuda_fp16.h>
#include <math.h>
#include <stdint.h>

// ---------------- problem constants ----------------
#define BB 2
#define TT 2048
#define DD 1024
#define HH 16
#define HD 64
#define STRIDE 8
#define MLPD 4096
#define BT (BB*TT)          // 4096 rows
#define D3 (3*DD)           // 3072

// ---------------- scratch buffers ----------------
__device__ __half g_xn [BT*DD];
__device__ __half g_o  [BT*DD];
__device__ __half g_xn2[BT*DD];
__device__ __half g_h  [BT*MLPD];
__device__ __half g_win[D3*DD];
__device__ __half g_wout[DD*DD];
__device__ __half g_w1 [MLPD*DD];
__device__ __half g_w2 [DD*MLPD];
__device__ __half g_qkv[BT*D3];
__device__ float g_x2 [BT*DD];

// ---------------- helpers ----------------
__device__ __forceinline__ uint32_t smem_u32(const void* p) {
    uint32_t a;
    asm("{ .reg .u64 t; cvta.to.shared.u64 t, %1; cvt.u32.u64 %0, t; }" : "=r"(a) : "l"(p));
    return a;
}
__device__ __forceinline__ void cp16(uint32_t dst, const void* src) {
    asm volatile("cp.async.cg.shared.global [%0], [%1], 16;" :: "r"(dst), "l"(src) : "memory");
}
__device__ __forceinline__ void ldmx4(uint32_t* r, uint32_t addr) {
    asm volatile("ldmatrix.sync.aligned.m8n8.x4.shared.b16 {%0,%1,%2,%3}, [%4];"
        : "=r"(r[0]), "=r"(r[1]), "=r"(r[2]), "=r"(r[3]) : "r"(addr));
}
__device__ __forceinline__ void ldmx4t(uint32_t* r, uint32_t addr) {
    asm volatile("ldmatrix.sync.aligned.m8n8.x4.trans.shared.b16 {%0,%1,%2,%3}, [%4];"
        : "=r"(r[0]), "=r"(r[1]), "=r"(r[2]), "=r"(r[3]) : "r"(addr));
}
__device__ __forceinline__ void mma_f16(float* c, const uint32_t* a, const uint32_t* b) {
    asm volatile("mma.sync.aligned.m16n8k16.row.col.f32.f16.f16.f32 "
        "{%0,%1,%2,%3}, {%4,%5,%6,%7}, {%8,%9}, {%0,%1,%2,%3};"
        : "+f"(c[0]), "+f"(c[1]), "+f"(c[2]), "+f"(c[3])
        : "r"(a[0]), "r"(a[1]), "r"(a[2]), "r"(a[3]), "r"(b[0]), "r"(b[1]));
}

// ---------------- GEMM config: CTA 128x256, GK=64, 3-stage ----------------
#define GM 128
#define GN 256
#define GK 64
#define AT_B 16384                  // A tile: 128 x 128B
#define STAGE_B 49152               // A 16KB + W 32KB
#define NST 3
#define GEMM_SMEM (NST*STAGE_B)     // 147456

// 128B rows, 16B chunks: chunk' = c ^ (r & 7)  -> conflict-free ldmatrix
#define SWO(r, c) ((uint32_t)((r) * 128 + (((c) ^ ((r) & 7)) & 7) * 16))

#define GEMM_PROLOG() \
    float acc[4][8][4]; \
    _Pragma("unroll") \
    for (int i_ = 0; i_ < 4; i_++) \
        _Pragma("unroll") \
        for (int j_ = 0; j_ < 8; j_++) \
            _Pragma("unroll") \
            for (int k_ = 0; k_ < 4; k_++) acc[i_][j_][k_] = 0.f; \
    const int la_row = lane & 15; \
    const int la_kh  = lane >> 4; \
    const int lb_row = (lane & 7) + ((lane >> 4) << 3); \
    const int lb_kh  = (lane >> 3) & 1;

#define GEMM_MAINLOOP(nch) \
    load_stage(0, 0); \
    load_stage(1, 1); \
    for (int i = 0; i < (nch); i++) { \
        asm volatile("cp.async.wait_group 1;" ::: "memory"); \
        __syncthreads(); \
        if (i + 2 < (nch)) load_stage(i + 2, (i + 2) % NST); \
        else asm volatile("cp.async.commit_group;" ::: "memory"); \
        const uint32_t aB = sb + (i % NST) * STAGE_B; \
        const uint32_t wB = aB + AT_B; \
        _Pragma("unroll") \
        for (int ks = 0; ks < 4; ks++) { \
            uint32_t b4[4][4]; \
            _Pragma("unroll") \
            for (int nf2 = 0; nf2 < 4; nf2++) { \
                const int r = wn + nf2 * 16 + lb_row; \
                ldmx4(b4[nf2], wB + SWO(r, ks * 2 + lb_kh)); \
            } \
            _Pragma("unroll") \
            for (int mf = 0; mf < 4; mf++) { \
                uint32_t a_[4]; \
                const int r = wm + mf * 16 + la_row; \
                ldmx4(a_, aB + SWO(r, ks * 2 + la_kh)); \
                _Pragma("unroll") \
                for (int nf2 = 0; nf2 < 4; nf2++) { \
                    mma_f16(acc[mf][2 * nf2 + 0], a_, &b4[nf2][0]); \
                    mma_f16(acc[mf][2 * nf2 + 1], a_, &b4[nf2][2]); \
                } \
            } \
        } \
    }

// ---------------- generic GEMM: C[M,N] = A @ W^T (+bias)(+gelu)(+res) ------
template<bool GELU_, bool RES_, bool F16O_>
__global__ void __launch_bounds__(256, 1) gemm_f16k(
    const __half* __restrict__ A, const __half* __restrict__ W,
    const float* __restrict__ bias, const float* __restrict__ Rres,
    float* __restrict__ C, __half* __restrict__ Cf, int N, int K)
{
    extern __shared__ char smem[];
    const uint32_t sb = smem_u32(smem);
    const int t = threadIdx.x;
    const int wid = t >> 5, lane = t & 31;
    const int m0 = blockIdx.y * GM;
    const int n0 = blockIdx.x * GN;
    const int wm = (wid & 1) * 64;
    const int wn = (wid >> 1) * 64;
    const int nch = K / GK;

    auto load_stage = [&](int chunk, int s) {
        const uint32_t base = sb + s * STAGE_B;
        #pragma unroll
        for (int j = 0; j < 4; j++) {
            const int idx = t + j * 256;
            const int r = idx >> 3, c = idx & 7;
            cp16(base + SWO(r, c), A + (size_t)(m0 + r) * K + (size_t)chunk * GK + c * 8);
        }
        #pragma unroll
        for (int j = 0; j < 8; j++) {
            const int idx = t + j * 256;
            const int r = idx >> 3, c = idx & 7;
            cp16(base + AT_B + SWO(r, c), W + (size_t)(n0 + r) * K + (size_t)chunk * GK + c * 8);
        }
        asm volatile("cp.async.commit_group;" ::: "memory");
    };

    GEMM_PROLOG();
    GEMM_MAINLOOP(nch);

    // epilogue
    const int er = lane >> 2;
    const int ec = (lane & 3) * 2;
    #pragma unroll
    for (int mf = 0; mf < 4; mf++) {
        #pragma unroll
        for (int nf = 0; nf < 8; nf++) {
            const int c0 = n0 + wn + nf * 8 + ec;
            const float b0 = bias[c0], b1 = bias[c0 + 1];
            #pragma unroll
            for (int half = 0; half < 2; half++) {
                const int r = m0 + wm + mf * 16 + er + half * 8;
                float v0 = acc[mf][nf][half * 2 + 0] + b0;
                float v1 = acc[mf][nf][half * 2 + 1] + b1;
                if (GELU_) {
                    v0 = 0.5f * v0 * (1.0f + erff(v0 * 0.70710678118654752f));
                    v1 = 0.5f * v1 * (1.0f + erff(v1 * 0.70710678118654752f));
                }
                if (RES_) {
                    v0 += Rres[(size_t)r * N + c0];
                    v1 += Rres[(size_t)r * N + c0 + 1];
                }
                if (F16O_) {
                    *(__half2*)(Cf + (size_t)r * N + c0) = __floats2half2_rn(v0, v1);
                } else {
                    float2 p; p.x = v0; p.y = v1;
                    *(float2*)(C + (size_t)r * N + c0) = p;
                }
            }
        }
    }
}

// ---------------- QKV kernel: kv blocks (all rows) + q blocks (rows%8==0) --
// grid (12, 32): bx<8 -> KV cols [1024,3072); bx>=8 -> Q cols [0,1024), by<4.
__global__ void __launch_bounds__(256, 1) qkv_kernel(
    const __half* __restrict__ Axn, const __half* __restrict__ win,
    const float* __restrict__ b_in, __half* __restrict__ qkv,
    __half* __restrict__ o)
{
    const bool kvb = blockIdx.x < 8;
    if (!kvb && blockIdx.y >= 4) return;
    extern __shared__ char smem[];
    const uint32_t sb = smem_u32(smem);
    const int t = threadIdx.x;
    const int wid = t >> 5, lane = t & 31;
    const int bx = kvb ? blockIdx.x : blockIdx.x - 8;
    const int rs = kvb ? 1 : 8;
    const int colOff = kvb ? 1024 : 0;
    const int m0 = blockIdx.y * GM;
    const int n0 = bx * GN;
    const int wm = (wid & 1) * 64;
    const int wn = (wid >> 1) * 64;
    const int K = DD;
    const int nch = K / GK;
    const __half* W = win + (size_t)(colOff + n0) * K;

    auto load_stage = [&](int chunk, int s) {
        const uint32_t base = sb + s * STAGE_B;
        #pragma unroll
        for (int j = 0; j < 4; j++) {
            const int idx = t + j * 256;
            const int r = idx >> 3, c = idx & 7;
            cp16(base + SWO(r, c), Axn + (size_t)((m0 + r) * rs) * K + (size_t)chunk * GK + c * 8);
        }
        #pragma unroll
        for (int j = 0; j < 8; j++) {
            const int idx = t + j * 256;
            const int r = idx >> 3, c = idx & 7;
            cp16(base + AT_B + SWO(r, c), W + (size_t)r * K + (size_t)chunk * GK + c * 8);
        }
        asm volatile("cp.async.commit_group;" ::: "memory");
    };

    GEMM_PROLOG();
    GEMM_MAINLOOP(nch);

    // epilogue: write qkv (f16); v-cols also write o for non-global rows
    const bool vblk = kvb && (bx >= 4);
    const int er = lane >> 2;
    const int ec = (lane & 3) * 2;
    #pragma unroll
    for (int mf = 0; mf < 4; mf++) {
        #pragma unroll
        for (int nf = 0; nf < 8; nf++) {
            const int g = colOff + n0 + wn + nf * 8 + ec;
            const float b0 = b_in[g], b1 = b_in[g + 1];
            #pragma unroll
            for (int half = 0; half < 2; half++) {
                const int r = (m0 + wm + mf * 16 + er + half * 8) * rs;
                const __half2 hv = __floats2half2_rn(
                    acc[mf][nf][half * 2 + 0] + b0,
                    acc[mf][nf][half * 2 + 1] + b1);
                *(__half2*)(qkv + (size_t)r * D3 + g) = hv;
                if (vblk && ((r & (TT - 1)) & (STRIDE - 1)) != 0)
                    *(__half2*)(o + (size_t)r * DD + g - 2048) = hv;
            }
        }
    }
}

// ---------------- LayerNorm -> f16 ----------------
__global__ __launch_bounds__(256) void ln_f16_kernel(
    const float* __restrict__ x, const float* __restrict__ g, const float* __restrict__ b,
    __half* __restrict__ y)
{
    const int row = blockIdx.x;
    const int tid = threadIdx.x;
    float4 v = ((const float4*)(x + (size_t)row * DD))[tid];

    float s  = v.x + v.y + v.z + v.w;
    float sq = v.x*v.x + v.y*v.y + v.z*v.z + v.w*v.w;
    __shared__ float red_s[8], red_q[8];
    for (int o = 16; o > 0; o >>= 1) {
        s  += __shfl_xor_sync(0xffffffffu, s,  o);
        sq += __shfl_xor_sync(0xffffffffu, sq, o);
    }
    const int wid = tid >> 5, lid = tid & 31;
    if (lid == 0) { red_s[wid] = s; red_q[wid] = sq; }
    __syncthreads();
    if (tid == 0) {
        float ts = 0.f, tq = 0.f;
        #pragma unroll
        for (int i = 0; i < 8; i++) { ts += red_s[i]; tq += red_q[i]; }
        red_s[0] = ts * (1.0f / DD);
        red_q[0] = tq * (1.0f / DD);
    }
    __syncthreads();
    const float mean = red_s[0];
    const float rstd = rsqrtf(red_q[0] - mean * mean + 1e-5f);

    const float4 gg = ((const float4*)g)[tid];
    const float4 bb = ((const float4*)b)[tid];
    float o0 = (v.x - mean) * rstd * gg.x + bb.x;
    float o1 = (v.y - mean) * rstd * gg.y + bb.y;
    float o2 = (v.z - mean) * rstd * gg.z + bb.z;
    float o3 = (v.w - mean) * rstd * gg.w + bb.w;
    __half2* py = (__half2*)(y + (size_t)row * DD);
    py[2*tid]   = __floats2half2_rn(o0, o1);
    py[2*tid+1] = __floats2half2_rn(o2, o3);
}

// ---------------- fused fp32 -> fp16 weight convert ----------------
#define CV0 (D3*DD/4)
#define CV1 (DD*DD/4)
#define CV2 (MLPD*DD/4)
#define CV3 (DD*MLPD/4)
__global__ __launch_bounds__(256) void cvt_all_kernel(
    const float* __restrict__ s0, __half* __restrict__ d0,
    const float* __restrict__ s1, __half* __restrict__ d1,
    const float* __restrict__ s2, __half* __restrict__ d2,
    const float* __restrict__ s3, __half* __restrict__ d3)
{
    int i = blockIdx.x * 256 + threadIdx.x;
    const float* src; __half* dst;
    if (i < CV0)                       { src = s0; dst = d0; }
    else if ((i -= CV0) < CV1)         { src = s1; dst = d1; }
    else if ((i -= CV1) < CV2)         { src = s2; dst = d2; }
    else if ((i -= CV2) < CV3)         { src = s3; dst = d3; }
    else return;
    float4 v = ((const float4*)src)[i];
    ((__half2*)dst)[2*i]   = __floats2half2_rn(v.x, v.y);
    ((__half2*)dst)[2*i+1] = __floats2half2_rn(v.z, v.w);
}

// ---------------- global rows: HMMA flash attention ----------------
#define AQ 32
#define CK 128
#define SS_ST 132
#define PS_ST 136
#define QS_OFF 0
#define KS_OFF 4608
#define VS_OFF (KS_OFF + 2*CK*144)
#define SS_OFF (VS_OFF + 2*CK*144)
#define PS_OFF (SS_OFF + AQ*SS_ST*4)
#define ML_OFF (PS_OFF + AQ*PS_ST*2)
#define ATTN_SMEM (ML_OFF + 3*AQ*4)

__global__ void __launch_bounds__(128, 2) attn_hmma_kernel(
    __half* __restrict__ o, const __half* __restrict__ qkv)
{
    extern __shared__ char smem[];
    const uint32_t sb = smem_u32(smem);
    float* Ss = (float*)(smem + SS_OFF);
    float* m_s = (float*)(smem + ML_OFF);
    float* l_s = m_s + AQ;
    float* corr_s = l_s + AQ;

    const int t = threadIdx.x;
    const int w = t >> 5, lane = t & 31;
    const int blk = blockIdx.x;
    const int qt = blk & 7;
    const int h  = (blk >> 3) & (HH - 1);
    const int b  = blk >> 7;

    {
        const __half2 sc = __floats2half2_rn(0.125f, 0.125f);
        #pragma unroll
        for (int j = 0; j < 2; j++) {
            const int idx = t + j * 128;
            const int q = idx >> 3, c = idx & 7;
            const int tq = (qt * AQ + q) * STRIDE;
            uint4 raw = *(const uint4*)(qkv + (size_t)(b * TT + tq) * D3 + h * HD + c * 8);
            __half2* hp = (__half2*)&raw;
            #pragma unroll
            for (int u = 0; u < 4; u++) hp[u] = __hmul2(hp[u], sc);
            *(uint4*)(smem + QS_OFF + q * 144 + c * 16) = raw;
        }
    }
    if (t < AQ) { m_s[t] = -1e30f; l_s[t] = 0.f; }
    __syncthreads();

    uint32_t aq[4][4];
    {
        const int r = (w & 1) * 16 + (lane & 15);
        #pragma unroll
        for (int ks = 0; ks < 4; ks++)
            ldmx4(aq[ks], sb + QS_OFF + (uint32_t)(r * 144) + (ks * 2 + (lane >> 4)) * 16);
    }

    auto load_kv = [&](int chunk, int s) {
        const int k0 = chunk * CK;
        const uint32_t kb = sb + KS_OFF + s * (CK * 144);
        const uint32_t vb = sb + VS_OFF + s * (CK * 144);
        #pragma unroll
        for (int j = 0; j < 8; j++) {
            const int idx = t + j * 128;
            const int r = idx >> 3, c = idx & 7;
            const size_t g = (size_t)(b * TT + k0 + r) * D3 + h * HD + c * 8;
            cp16(kb + r * 144 + c * 16, qkv + DD + g);
            cp16(vb + r * 144 + c * 16, qkv + 2 * DD + g);
        }
        asm volatile("cp.async.commit_group;" ::: "memory");
    };

    float oacc[4][4];
    #pragma unroll
    for (int i = 0; i < 4; i++)
        #pragma unroll
        for (int j = 0; j < 4; j++) oacc[i][j] = 0.f;

    load_kv(0, 0);

    const int lb_row = (lane & 7) + ((lane >> 4) << 3);
    const int lb_kh  = (lane >> 3) & 1;

    for (int ch = 0; ch < TT / CK; ch++) {
        if (ch + 1 < TT / CK) load_kv(ch + 1, (ch + 1) & 1);
        else asm volatile("cp.async.commit_group;" ::: "memory");
        asm volatile("cp.async.wait_group 1;" ::: "memory");
        __syncthreads();
        const uint32_t kB = sb + KS_OFF + (ch & 1) * (CK * 144);
        const uint32_t vB = sb + VS_OFF + (ch & 1) * (CK * 144);

        float sacc[8][4];
        #pragma unroll
        for (int i = 0; i < 8; i++)
            #pragma unroll
            for (int j = 0; j < 4; j++) sacc[i][j] = 0.f;
        #pragma unroll
        for (int ks = 0; ks < 4; ks++) {
            uint32_t b4[4][4];
            #pragma unroll
            for (int nf2 = 0; nf2 < 4; nf2++) {
                const int r = (w >> 1) * 64 + nf2 * 16 + lb_row;
                ldmx4(b4[nf2], kB + (uint32_t)(r * 144) + (ks * 2 + lb_kh) * 16);
            }
            #pragma unroll
            for (int nf2 = 0; nf2 < 4; nf2++) {
                mma_f16(sacc[2 * nf2 + 0], aq[ks], &b4[nf2][0]);
                mma_f16(sacc[2 * nf2 + 1], aq[ks], &b4[nf2][2]);
            }
        }
        {
            const int row0 = (w & 1) * 16 + (lane >> 2);
            #pragma unroll
            for (int nf = 0; nf < 8; nf++) {
                const int col = (w >> 1) * 64 + nf * 8 + (lane & 3) * 2;
                Ss[row0 * SS_ST + col]       = sacc[nf][0];
                Ss[row0 * SS_ST + col + 1]   = sacc[nf][1];
                Ss[(row0 + 8) * SS_ST + col]     = sacc[nf][2];
                Ss[(row0 + 8) * SS_ST + col + 1] = sacc[nf][3];
            }
        }
        __syncthreads();

        {
            const int q = t >> 2;
            const int kseg = (t & 3) * 32;
            float4 sv[8];
            #pragma unroll
            for (int i = 0; i < 8; i++)
                sv[i] = *(float4*)(Ss + q * SS_ST + kseg + i * 4);
            float mx = -1e30f;
            #pragma unroll
            for (int i = 0; i < 8; i++)
                mx = fmaxf(mx, fmaxf(fmaxf(sv[i].x, sv[i].y), fmaxf(sv[i].z, sv[i].w)));
            mx = fmaxf(mx, __shfl_xor_sync(0xffffffffu, mx, 1));
            mx = fmaxf(mx, __shfl_xor_sync(0xffffffffu, mx, 2));
            const float m_old = m_s[q];
            const float mnew = fmaxf(m_old, mx);
            float lsum = 0.f;
            __half* pp = (__half*)(smem + PS_OFF) + q * PS_ST + kseg;
            #pragma unroll
            for (int i = 0; i < 8; i++) {
                float e0 = expf(sv[i].x - mnew), e1 = expf(sv[i].y - mnew);
                float e2 = expf(sv[i].z - mnew), e3 = expf(sv[i].w - mnew);
                lsum += e0 + e1 + e2 + e3;
                ((__half2*)(pp + i * 4))[0] = __floats2half2_rn(e0, e1);
                ((__half2*)(pp + i * 4))[1] = __floats2half2_rn(e2, e3);
            }
            lsum += __shfl_xor_sync(0xffffffffu, lsum, 1);
            lsum += __shfl_xor_sync(0xffffffffu, lsum, 2);
            if ((t & 3) == 0) {
                const float corr = expf(m_old - mnew);
                corr_s[q] = corr;
                l_s[q] = l_s[q] * corr + lsum;
                m_s[q] = mnew;
            }
        }
        __syncthreads();

        {
            const int row0 = (w & 1) * 16 + (lane >> 2);
            const float c0 = corr_s[row0];
            const float c1 = corr_s[row0 + 8];
            #pragma unroll
            for (int nf = 0; nf < 4; nf++) {
                oacc[nf][0] *= c0; oacc[nf][1] *= c0;
                oacc[nf][2] *= c1; oacc[nf][3] *= c1;
            }
            const int arow = (w & 1) * 16 + (lane & 15);
            #pragma unroll
            for (int ks = 0; ks < 8; ks++) {
                uint32_t ap[4];
                ldmx4(ap, sb + PS_OFF + (uint32_t)(arow * 272) + (ks * 2 + (lane >> 4)) * 16);
                #pragma unroll
                for (int nf2 = 0; nf2 < 2; nf2++) {
                    uint32_t bv[4];
                    const int krow = ks * 16 + (lane & 7) + ((lane >> 3) & 1) * 8;
                    const int dcol = (w >> 1) * 32 + nf2 * 16 + (lane >> 4) * 8;
                    ldmx4t(bv, vB + (uint32_t)(krow * 144) + dcol * 2);
                    mma_f16(oacc[2 * nf2 + 0], ap, &bv[0]);
                    mma_f16(oacc[2 * nf2 + 1], ap, &bv[2]);
                }
            }
        }
        __syncthreads();
    }

    {
        const int row0 = (w & 1) * 16 + (lane >> 2);
        const float i0 = 1.0f / l_s[row0];
        const float i1 = 1.0f / l_s[row0 + 8];
        #pragma unroll
        for (int nf = 0; nf < 4; nf++) {
            const int d = (w >> 1) * 32 + nf * 8 + (lane & 3) * 2;
            const int tq0 = (qt * AQ + row0) * STRIDE;
            const int tq1 = (qt * AQ + row0 + 8) * STRIDE;
            *(__half2*)(o + (size_t)(b * TT + tq0) * DD + h * HD + d) =
                __floats2half2_rn(oacc[nf][0] * i0, oacc[nf][1] * i0);
            *(__half2*)(o + (size_t)(b * TT + tq1) * DD + h * HD + d) =
                __floats2half2_rn(oacc[nf][2] * i1, oacc[nf][3] * i1);
        }
    }
}

// ---------------- launch ----------------
extern "C" void kernel_launch(void* const* d_in, const int* in_sizes, int n_in,
                              void* d_out, int out_size)
{
    const float* x     = (const float*)d_in[0];
    const float* w_in  = (const float*)d_in[1];
    const float* b_in  = (const float*)d_in[2];
    const float* w_out = (const float*)d_in[3];
    const float* b_out = (const float*)d_in[4];
    const float* w1    = (const float*)d_in[5];
    const float* b1    = (const float*)d_in[6];
    const float* w2    = (const float*)d_in[7];
    const float* b2    = (const float*)d_in[8];
    const float* ln1_g = (const float*)d_in[9];
    const float* ln1_b = (const float*)d_in[10];
    const float* ln2_g = (const float*)d_in[11];
    const float* ln2_b = (const float*)d_in[12];
    float* out = (float*)d_out;

    __half *xn,*o,*xn2,*hbuf,*win,*wout,*w1h,*w2h,*qkv;
    float *x2;
    cudaGetSymbolAddress((void**)&xn,   g_xn);
    cudaGetSymbolAddress((void**)&o,    g_o);
    cudaGetSymbolAddress((void**)&xn2,  g_xn2);
    cudaGetSymbolAddress((void**)&hbuf, g_h);
    cudaGetSymbolAddress((void**)&win,  g_win);
    cudaGetSymbolAddress((void**)&wout, g_wout);
    cudaGetSymbolAddress((void**)&w1h,  g_w1);
    cudaGetSymbolAddress((void**)&w2h,  g_w2);
    cudaGetSymbolAddress((void**)&qkv,  g_qkv);
    cudaGetSymbolAddress((void**)&x2,   g_x2);

    cudaFuncSetAttribute(qkv_kernel, cudaFuncAttributeMaxDynamicSharedMemorySize, GEMM_SMEM);
    cudaFuncSetAttribute(gemm_f16k<false,true ,false>, cudaFuncAttributeMaxDynamicSharedMemorySize, GEMM_SMEM);
    cudaFuncSetAttribute(gemm_f16k<true ,false,true >, cudaFuncAttributeMaxDynamicSharedMemorySize, GEMM_SMEM);
    cudaFuncSetAttribute(attn_hmma_kernel, cudaFuncAttributeMaxDynamicSharedMemorySize, ATTN_SMEM);

    // 1. LN1 -> f16
    ln_f16_kernel<<<BT, 256>>>(x, ln1_g, ln1_b, xn);
    // 2. convert all weights -> f16
    cvt_all_kernel<<<(CV0 + CV1 + CV2 + CV3 + 255) / 256, 256>>>(
        w_in, win, w_out, wout, w1, w1h, w2, w2h);
    // 3. QKV (kv: all rows; q: global rows only; v-copy fused)
    qkv_kernel<<<dim3(12, 32), 256, GEMM_SMEM>>>(xn, win, b_in, qkv, o);
    // 4. attention (global rows)
    attn_hmma_kernel<<<BB*HH*8, 128, ATTN_SMEM>>>(o, qkv);
    // 5. out-proj + residual -> x2 fp32
    gemm_f16k<false,true,false><<<dim3(DD/GN, BT/GM), 256, GEMM_SMEM>>>(
        o, wout, b_out, x, x2, nullptr, DD, DD);
    // 6. LN2 -> f16
    ln_f16_kernel<<<BT, 256>>>(x2, ln2_g, ln2_b, xn2);
    // 7. MLP1 + GELU -> h f16
    gemm_f16k<true,false,true><<<dim3(MLPD/GN, BT/GM), 256, GEMM_SMEM>>>(
        xn2, w1h, b1, nullptr, nullptr, hbuf, MLPD, DD);
    // 8. MLP2 + residual -> out fp32
    gemm_f16k<false,true,false><<<dim3(DD/GN, BT/GM), 256, GEMM_SMEM>>>(
        hbuf, w2h, b2, x2, out, nullptr, DD, MLPD);
}